// round 6
// baseline (speedup 1.0000x reference)
#include <cuda_runtime.h>

#define N_NODES 100000
#define THREADS 256

// floats: dinv[N] | h[64N] | h1[64N] | t2[32N] | h2agg[32N] | logits[32N] | nrm[E]
// ints:   rowptr[N] | degI[N] | cnt[N] | csr_src[E]
__device__ float g_scratch[26100000];

// ---------------------------------------------------------------- zero (ints/floats, 16B chunks)
__global__ void k_zero(float4* __restrict__ p, int n4) {
    int i = blockIdx.x * blockDim.x + threadIdx.x;
    int stride = gridDim.x * blockDim.x;
    float4 z = make_float4(0.f, 0.f, 0.f, 0.f);
    for (; i < n4; i += stride) p[i] = z;
}

// ---------------------------------------------------------------- degree histogram (int)
__global__ void k_deg(const int* __restrict__ ei, int* __restrict__ degI, int E) {
    int e = blockIdx.x * blockDim.x + threadIdx.x;
    if (e >= E) return;
    atomicAdd(&degI[ei[E + e]], 1);
}

// ---------------------------------------------------------------- single-block exclusive scan + dinv
__global__ __launch_bounds__(1024) void k_scan(const int* __restrict__ degI,
                                               int* __restrict__ rowptr,
                                               float* __restrict__ dinv, int N) {
    __shared__ int sh[1024];
    int t = threadIdx.x;
    int chunk = (N + 1023) >> 10;
    int lo = t * chunk;
    int hi = min(lo + chunk, N);
    int sum = 0;
    for (int i = lo; i < hi; i++) sum += degI[i];
    sh[t] = sum;
    __syncthreads();
    for (int off = 1; off < 1024; off <<= 1) {
        int v = (t >= off) ? sh[t - off] : 0;
        __syncthreads();
        sh[t] += v;
        __syncthreads();
    }
    int run = sh[t] - sum;  // exclusive prefix of this thread's chunk
    for (int i = lo; i < hi; i++) {
        int d = degI[i];
        rowptr[i] = run;
        run += d;
        dinv[i] = rsqrtf((float)d + 1.0f);
    }
}

// ---------------------------------------------------------------- CSR fill: bucket edges by dst
__global__ void k_fill(const int* __restrict__ ei, const int* __restrict__ rowptr,
                       int* __restrict__ cnt, const float* __restrict__ dinv,
                       int* __restrict__ csr_src, float* __restrict__ csr_nrm, int E) {
    int e = blockIdx.x * blockDim.x + threadIdx.x;
    if (e >= E) return;
    int s = ei[e];
    int d = ei[E + e];
    int slot = rowptr[d] + atomicAdd(&cnt[d], 1);
    csr_src[slot] = s;
    csr_nrm[slot] = dinv[s] * dinv[d];
}

// ---------------------------------------------------------------- GEMM1 fused: [h | logits] = x @ [W1 | Wl0]
__global__ __launch_bounds__(384) void k_gemm_f1(
    const float* __restrict__ A, const float* __restrict__ W1, const float* __restrict__ Wl,
    float* __restrict__ H, float* __restrict__ L, int M) {
    __shared__ float As[16][132];
    __shared__ float Bs[16][96];
    int tid = threadIdx.x;
    int tr = tid / 24, tc = tid % 24;
    int rowBase = blockIdx.x * 128;
    float acc[8][4];
#pragma unroll
    for (int i = 0; i < 8; i++)
#pragma unroll
        for (int j = 0; j < 4; j++) acc[i][j] = 0.f;

    for (int k0 = 0; k0 < 128; k0 += 16) {
        for (int i = tid; i < 512; i += 384) {
            int r = i >> 2, c4 = i & 3;
            int gr = rowBase + r;
            float4 v = (gr < M) ? *(const float4*)(A + (size_t)gr * 128 + k0 + c4 * 4)
                                : make_float4(0.f, 0.f, 0.f, 0.f);
            As[c4 * 4 + 0][r] = v.x; As[c4 * 4 + 1][r] = v.y;
            As[c4 * 4 + 2][r] = v.z; As[c4 * 4 + 3][r] = v.w;
        }
        for (int i = tid; i < 1536; i += 384) {
            int r = i / 96, c = i % 96;
            Bs[r][c] = (c < 64) ? W1[(size_t)(k0 + r) * 64 + c]
                                : Wl[(size_t)(k0 + r) * 32 + (c - 64)];
        }
        __syncthreads();
#pragma unroll
        for (int kk = 0; kk < 16; kk++) {
            float4 a0 = *(const float4*)&As[kk][tr * 8];
            float4 a1 = *(const float4*)&As[kk][tr * 8 + 4];
            float4 bv = *(const float4*)&Bs[kk][tc * 4];
            float a[8] = {a0.x, a0.y, a0.z, a0.w, a1.x, a1.y, a1.z, a1.w};
            float b[4] = {bv.x, bv.y, bv.z, bv.w};
#pragma unroll
            for (int i = 0; i < 8; i++)
#pragma unroll
                for (int j = 0; j < 4; j++) acc[i][j] += a[i] * b[j];
        }
        __syncthreads();
    }
#pragma unroll
    for (int i = 0; i < 8; i++) {
        int gr = rowBase + tr * 8 + i;
        if (gr >= M) continue;
        float4 v = make_float4(acc[i][0], acc[i][1], acc[i][2], acc[i][3]);
        if (tc < 16) *(float4*)(H + (size_t)gr * 64 + tc * 4) = v;
        else         *(float4*)(L + (size_t)gr * 32 + (tc - 16) * 4) = v;
    }
}

// ---------------------------------------------------------------- GEMM2 fused: [t2 | logits+=] = h1 @ [W2 | Wl1]
__global__ __launch_bounds__(256) void k_gemm_f2(
    const float* __restrict__ A, const float* __restrict__ W2, const float* __restrict__ Wl,
    float* __restrict__ T2, float* __restrict__ L, int M) {
    __shared__ float As[16][132];
    __shared__ float Bs[16][64];
    int tid = threadIdx.x;
    int tr = tid / 16, tc = tid % 16;
    int rowBase = blockIdx.x * 128;
    float acc[8][4];
#pragma unroll
    for (int i = 0; i < 8; i++)
#pragma unroll
        for (int j = 0; j < 4; j++) acc[i][j] = 0.f;

    for (int k0 = 0; k0 < 64; k0 += 16) {
        for (int i = tid; i < 512; i += 256) {
            int r = i >> 2, c4 = i & 3;
            int gr = rowBase + r;
            float4 v = (gr < M) ? *(const float4*)(A + (size_t)gr * 64 + k0 + c4 * 4)
                                : make_float4(0.f, 0.f, 0.f, 0.f);
            As[c4 * 4 + 0][r] = v.x; As[c4 * 4 + 1][r] = v.y;
            As[c4 * 4 + 2][r] = v.z; As[c4 * 4 + 3][r] = v.w;
        }
        for (int i = tid; i < 1024; i += 256) {
            int r = i / 64, c = i % 64;
            Bs[r][c] = (c < 32) ? W2[(size_t)(k0 + r) * 32 + c]
                                : Wl[(size_t)(128 + k0 + r) * 32 + (c - 32)];
        }
        __syncthreads();
#pragma unroll
        for (int kk = 0; kk < 16; kk++) {
            float4 a0 = *(const float4*)&As[kk][tr * 8];
            float4 a1 = *(const float4*)&As[kk][tr * 8 + 4];
            float4 bv = *(const float4*)&Bs[kk][tc * 4];
            float a[8] = {a0.x, a0.y, a0.z, a0.w, a1.x, a1.y, a1.z, a1.w};
            float b[4] = {bv.x, bv.y, bv.z, bv.w};
#pragma unroll
            for (int i = 0; i < 8; i++)
#pragma unroll
                for (int j = 0; j < 4; j++) acc[i][j] += a[i] * b[j];
        }
        __syncthreads();
    }
#pragma unroll
    for (int i = 0; i < 8; i++) {
        int gr = rowBase + tr * 8 + i;
        if (gr >= M) continue;
        if (tc < 8) {
            *(float4*)(T2 + (size_t)gr * 32 + tc * 4) =
                make_float4(acc[i][0], acc[i][1], acc[i][2], acc[i][3]);
        } else {
            float* p = L + (size_t)gr * 32 + (tc - 8) * 4;
            float4 old = *(float4*)p;
            *(float4*)p = make_float4(old.x + acc[i][0], old.y + acc[i][1],
                                      old.z + acc[i][2], old.w + acc[i][3]);
        }
    }
}

// ---------------------------------------------------------------- GEMM3 fused: logits += (h2agg + t2*dinv^2 + b2) @ Wl2
__global__ __launch_bounds__(128) void k_gemm_f3(
    const float* __restrict__ AGG, const float* __restrict__ T2,
    const float* __restrict__ dinv, const float* __restrict__ b2,
    const float* __restrict__ Wl2, float* __restrict__ L, int M) {
    __shared__ float As[32][132];
    __shared__ float Bs[32][32];
    int tid = threadIdx.x;
    int tr = tid / 8, tc = tid % 8;
    int rowBase = blockIdx.x * 128;

    for (int i = tid; i < 1024; i += 128) {
        int r = i >> 3, c4 = i & 7;
        int gr = rowBase + r;
        float4 v = make_float4(0.f, 0.f, 0.f, 0.f);
        if (gr < M) {
            float di = dinv[gr]; float d2 = di * di;
            float4 ag = *(const float4*)(AGG + (size_t)gr * 32 + c4 * 4);
            float4 tv = *(const float4*)(T2  + (size_t)gr * 32 + c4 * 4);
            float4 bv = *(const float4*)(b2 + c4 * 4);
            v = make_float4(ag.x + tv.x * d2 + bv.x, ag.y + tv.y * d2 + bv.y,
                            ag.z + tv.z * d2 + bv.z, ag.w + tv.w * d2 + bv.w);
        }
        As[c4 * 4 + 0][r] = v.x; As[c4 * 4 + 1][r] = v.y;
        As[c4 * 4 + 2][r] = v.z; As[c4 * 4 + 3][r] = v.w;
    }
    for (int i = tid; i < 1024; i += 128) Bs[i >> 5][i & 31] = Wl2[i];
    __syncthreads();

    float acc[8][4];
#pragma unroll
    for (int i = 0; i < 8; i++)
#pragma unroll
        for (int j = 0; j < 4; j++) acc[i][j] = 0.f;
#pragma unroll
    for (int kk = 0; kk < 32; kk++) {
        float4 a0 = *(const float4*)&As[kk][tr * 8];
        float4 a1 = *(const float4*)&As[kk][tr * 8 + 4];
        float4 bv = *(const float4*)&Bs[kk][tc * 4];
        float a[8] = {a0.x, a0.y, a0.z, a0.w, a1.x, a1.y, a1.z, a1.w};
        float b[4] = {bv.x, bv.y, bv.z, bv.w};
#pragma unroll
        for (int i = 0; i < 8; i++)
#pragma unroll
            for (int j = 0; j < 4; j++) acc[i][j] += a[i] * b[j];
    }
#pragma unroll
    for (int i = 0; i < 8; i++) {
        int gr = rowBase + tr * 8 + i;
        if (gr >= M) continue;
        float* p = L + (size_t)gr * 32 + tc * 4;
        float4 old = *(float4*)p;
        *(float4*)p = make_float4(old.x + acc[i][0], old.y + acc[i][1],
                                  old.z + acc[i][2], old.w + acc[i][3]);
    }
}

// ---------------------------------------------------------------- gather, C=64: h1 = relu(sum + h*dinv^2 + b1)
__global__ __launch_bounds__(256) void k_gather64(
    const int* __restrict__ rowptr, const int* __restrict__ degI,
    const int* __restrict__ csr_src, const float* __restrict__ csr_nrm,
    const float* __restrict__ h, const float* __restrict__ dinv,
    const float* __restrict__ b1, float* __restrict__ h1, int N) {
    int node = blockIdx.x * 8 + (threadIdx.x >> 5);
    if (node >= N) return;
    int lane = threadIdx.x & 31;
    int j = rowptr[node];
    int end = j + degI[node];
    float2 acc = make_float2(0.f, 0.f);
    for (; j + 1 < end; j += 2) {
        int s0 = __ldg(csr_src + j);
        int s1 = __ldg(csr_src + j + 1);
        float n0 = __ldg(csr_nrm + j);
        float n1 = __ldg(csr_nrm + j + 1);
        float2 v0 = *(const float2*)(h + (size_t)s0 * 64 + lane * 2);
        float2 v1 = *(const float2*)(h + (size_t)s1 * 64 + lane * 2);
        acc.x += v0.x * n0 + v1.x * n1;
        acc.y += v0.y * n0 + v1.y * n1;
    }
    if (j < end) {
        int s = __ldg(csr_src + j);
        float n = __ldg(csr_nrm + j);
        float2 v = *(const float2*)(h + (size_t)s * 64 + lane * 2);
        acc.x += v.x * n; acc.y += v.y * n;
    }
    float di = dinv[node]; float d2 = di * di;
    float2 hv = *(const float2*)(h + (size_t)node * 64 + lane * 2);
    float2 bv = *(const float2*)(b1 + lane * 2);
    float2 o = make_float2(fmaxf(acc.x + hv.x * d2 + bv.x, 0.f),
                           fmaxf(acc.y + hv.y * d2 + bv.y, 0.f));
    *(float2*)(h1 + (size_t)node * 64 + lane * 2) = o;
}

// ---------------------------------------------------------------- gather, C=32: pure aggregation
__global__ __launch_bounds__(256) void k_gather32(
    const int* __restrict__ rowptr, const int* __restrict__ degI,
    const int* __restrict__ csr_src, const float* __restrict__ csr_nrm,
    const float* __restrict__ t2, float* __restrict__ agg, int N) {
    int node = blockIdx.x * 8 + (threadIdx.x >> 5);
    if (node >= N) return;
    int lane = threadIdx.x & 31;
    int j = rowptr[node];
    int end = j + degI[node];
    float acc = 0.f;
    for (; j + 1 < end; j += 2) {
        int s0 = __ldg(csr_src + j);
        int s1 = __ldg(csr_src + j + 1);
        float n0 = __ldg(csr_nrm + j);
        float n1 = __ldg(csr_nrm + j + 1);
        acc += t2[(size_t)s0 * 32 + lane] * n0 + t2[(size_t)s1 * 32 + lane] * n1;
    }
    if (j < end) {
        acc += t2[(size_t)__ldg(csr_src + j) * 32 + lane] * __ldg(csr_nrm + j);
    }
    agg[(size_t)node * 32 + lane] = acc;
}

// ---------------------------------------------------------------- log_softmax over 32 cols, warp per node
__global__ void k_lsm(const float* __restrict__ logits, const float* __restrict__ bl,
                      float* __restrict__ out, int N) {
    int node = blockIdx.x * 8 + (threadIdx.x >> 5);
    int lane = threadIdx.x & 31;
    if (node >= N) return;
    float v = logits[(size_t)node * 32 + lane] + bl[lane];
    float m = v;
#pragma unroll
    for (int o = 16; o > 0; o >>= 1) m = fmaxf(m, __shfl_xor_sync(0xffffffffu, m, o));
    float ex = expf(v - m);
    float s = ex;
#pragma unroll
    for (int o = 16; o > 0; o >>= 1) s += __shfl_xor_sync(0xffffffffu, s, o);
    out[(size_t)node * 32 + lane] = v - m - logf(s);
}

// ----------------------------------------------------------------
extern "C" void kernel_launch(void* const* d_in, const int* in_sizes, int n_in,
                              void* d_out, int out_size) {
    const float* x  = (const float*)d_in[0];
    const int*   ei = (const int*)d_in[1];
    const float* W1 = (const float*)d_in[2];
    const float* b1 = (const float*)d_in[3];
    const float* W2 = (const float*)d_in[4];
    const float* b2 = (const float*)d_in[5];
    const float* Wl = (const float*)d_in[6];
    const float* bl = (const float*)d_in[7];
    float*       out = (float*)d_out;

    int M = in_sizes[0] / 128;   // 100000
    int E = in_sizes[1] / 2;     // 1600000

    float* s = nullptr;
    cudaGetSymbolAddress((void**)&s, g_scratch);
    float* dinv    = s;
    float* h       = dinv + N_NODES;
    float* h1      = h + (size_t)N_NODES * 64;
    float* t2      = h1 + (size_t)N_NODES * 64;
    float* h2agg   = t2 + (size_t)N_NODES * 32;
    float* logits  = h2agg + (size_t)N_NODES * 32;
    float* csr_nrm = logits + (size_t)N_NODES * 32;
    int*   rowptr  = (int*)(csr_nrm + 1600000);
    int*   degI    = rowptr + N_NODES;
    int*   cnt     = degI + N_NODES;
    int*   csr_src = cnt + N_NODES;

    // zero degI + cnt (contiguous 2N ints)
    k_zero<<<64, THREADS>>>((float4*)degI, (2 * M) / 4);

    // degree -> scan (rowptr, dinv) -> CSR fill (src, norm)
    k_deg<<<(E + THREADS - 1) / THREADS, THREADS>>>(ei, degI, E);
    k_scan<<<1, 1024>>>(degI, rowptr, dinv, M);
    k_fill<<<(E + THREADS - 1) / THREADS, THREADS>>>(ei, rowptr, cnt, dinv,
                                                     csr_src, csr_nrm, E);

    int gb = (M + 127) / 128;
    int gw = (M + 7) / 8;

    // layer 1 (+ x@Wl0), gather fused with self-loop + bias + relu
    k_gemm_f1<<<gb, 384>>>(x, W1, Wl, h, logits, M);
    k_gather64<<<gw, THREADS>>>(rowptr, degI, csr_src, csr_nrm, h, dinv, b1, h1, M);

    // layer 2 (+ h1@Wl1), pure gather
    k_gemm_f2<<<gb, 256>>>(h1, W2, Wl, t2, logits, M);
    k_gather32<<<gw, THREADS>>>(rowptr, degI, csr_src, csr_nrm, t2, h2agg, M);

    // final: epilogue-fused h2 @ Wl2
    k_gemm_f3<<<gb, 128>>>(h2agg, t2, dinv, b2, Wl + 192 * 32, logits, M);

    // log_softmax
    k_lsm<<<gw, THREADS>>>(logits, bl, out, M);
}

// round 10
// speedup vs baseline: 1.0856x; 1.0856x over previous
#include <cuda_runtime.h>
#include <mma.h>

using namespace nvcuda;

#define N_NODES 100000
#define NP      100032   // padded to multiple of 64
#define THREADS 256
#define E_MAX   1600000

// floats: dinv[NP] | h1[64NP] | h2agg[32NP] | h[64NP] | t2[32NP] | logits[32NP] | norm[E]
__device__ float g_scratch[(size_t)NP * 225 + E_MAX];

// ---------------------------------------------------------------- zero
__global__ void k_zero(float4* __restrict__ p, int n4) {
    int i = blockIdx.x * blockDim.x + threadIdx.x;
    int stride = gridDim.x * blockDim.x;
    float4 z = make_float4(0.f, 0.f, 0.f, 0.f);
    for (; i < n4; i += stride) p[i] = z;
}

// ---------------------------------------------------------------- degree (float RED into dinv buffer)
__global__ void k_deg(const int* __restrict__ ei, float* __restrict__ deg, int E) {
    int e = blockIdx.x * blockDim.x + threadIdx.x;
    if (e >= E) return;
    asm volatile("red.global.add.f32 [%0], %1;" :: "l"(deg + ei[E + e]), "f"(1.0f) : "memory");
}

__global__ void k_dinv(float* __restrict__ dinv, int N) {
    int i = blockIdx.x * blockDim.x + threadIdx.x;
    if (i < N) dinv[i] = rsqrtf(dinv[i] + 1.0f);
}

__global__ void k_norm(const int* __restrict__ ei, const float* __restrict__ dinv,
                       float* __restrict__ norm, int E) {
    int e = blockIdx.x * blockDim.x + threadIdx.x;
    if (e >= E) return;
    norm[e] = dinv[ei[e]] * dinv[ei[E + e]];
}

// ---------------------------------------------------------------- helpers for 3xTF32 split
__device__ __forceinline__ void split_tf32(float f, float& hi, float& lo) {
    hi = wmma::__float_to_tf32(f);
    lo = wmma::__float_to_tf32(f - hi);
}

typedef wmma::fragment<wmma::matrix_a, 16, 16, 8, wmma::precision::tf32, wmma::row_major> FragA;
typedef wmma::fragment<wmma::matrix_b, 16, 16, 8, wmma::precision::tf32, wmma::row_major> FragB;
typedef wmma::fragment<wmma::accumulator, 16, 16, 8, float> FragC;

__device__ __forceinline__ void mma3(FragC& acc, const FragA& ah, const FragA& al,
                                     const FragB& bh, const FragB& bl) {
    wmma::mma_sync(acc, ah, bh, acc);
    wmma::mma_sync(acc, ah, bl, acc);
    wmma::mma_sync(acc, al, bh, acc);
}

// ---------------------------------------------------------------- GEMM1: [h | logits] = x @ [W1 | Wl0]
// block: 64 rows x 96 cols, 8 warps (4M x 2N-groups of 3 n-tiles), K=128 in chunks of 32
__global__ __launch_bounds__(256) void k_gemm1_tc(
    const float* __restrict__ A, const float* __restrict__ W1, const float* __restrict__ Wl,
    float* __restrict__ H, float* __restrict__ L, int M) {
    __shared__ float Ah[64 * 40], Al[64 * 40];
    __shared__ float Bh[32 * 104], Bl[32 * 104];
    int tid = threadIdx.x;
    int warp = tid >> 5;
    int wm = warp & 3, wn = warp >> 2;
    int rowBase = blockIdx.x * 64;

    FragC acc[3];
#pragma unroll
    for (int t = 0; t < 3; t++) wmma::fill_fragment(acc[t], 0.f);

    for (int k0 = 0; k0 < 128; k0 += 32) {
        // A chunk 64x32
#pragma unroll
        for (int it = 0; it < 2; it++) {
            int i = tid + it * 256;                 // 512 float4
            int r = i >> 3, c4 = i & 7;
            int gr = rowBase + r;
            float4 v = (gr < M) ? *(const float4*)(A + (size_t)gr * 128 + k0 + c4 * 4)
                                : make_float4(0.f, 0.f, 0.f, 0.f);
            float* ph = Ah + r * 40 + c4 * 4;
            float* pl = Al + r * 40 + c4 * 4;
            split_tf32(v.x, ph[0], pl[0]); split_tf32(v.y, ph[1], pl[1]);
            split_tf32(v.z, ph[2], pl[2]); split_tf32(v.w, ph[3], pl[3]);
        }
        // B chunk 32x96
        for (int i = tid; i < 3072; i += 256) {
            int r = i / 96, c = i - r * 96;
            float f = (c < 64) ? W1[(size_t)(k0 + r) * 64 + c]
                               : Wl[(size_t)(k0 + r) * 32 + (c - 64)];
            split_tf32(f, Bh[r * 104 + c], Bl[r * 104 + c]);
        }
        __syncthreads();
#pragma unroll
        for (int kk = 0; kk < 32; kk += 8) {
            FragA ah, al;
            wmma::load_matrix_sync(ah, Ah + wm * 16 * 40 + kk, 40);
            wmma::load_matrix_sync(al, Al + wm * 16 * 40 + kk, 40);
#pragma unroll
            for (int t = 0; t < 3; t++) {
                int nt = wn * 3 + t;
                FragB bh, bl;
                wmma::load_matrix_sync(bh, Bh + kk * 104 + nt * 16, 104);
                wmma::load_matrix_sync(bl, Bl + kk * 104 + nt * 16, 104);
                mma3(acc[t], ah, al, bh, bl);
            }
        }
        __syncthreads();
    }
    int gr0 = rowBase + wm * 16;   // always < NP (buffers padded)
#pragma unroll
    for (int t = 0; t < 3; t++) {
        int nt = wn * 3 + t;
        if (nt < 4)
            wmma::store_matrix_sync(H + (size_t)gr0 * 64 + nt * 16, acc[t], 64, wmma::mem_row_major);
        else
            wmma::store_matrix_sync(L + (size_t)gr0 * 32 + (nt - 4) * 16, acc[t], 32, wmma::mem_row_major);
    }
}

// ---------------------------------------------------------------- GEMM2: [t2 | logits+=] = h1 @ [W2 | Wl1]
// block 64x64, K=64 in chunks of 32; h1 padded -> no row guards
__global__ __launch_bounds__(256) void k_gemm2_tc(
    const float* __restrict__ A, const float* __restrict__ W2, const float* __restrict__ Wl,
    float* __restrict__ T2, float* __restrict__ L) {
    __shared__ float Ah[64 * 40], Al[64 * 40];
    __shared__ float Bh[32 * 72], Bl[32 * 72];
    int tid = threadIdx.x;
    int warp = tid >> 5;
    int wm = warp & 3, wn = warp >> 2;
    int rowBase = blockIdx.x * 64;

    FragC acc[2];
    wmma::fill_fragment(acc[0], 0.f);
    wmma::fill_fragment(acc[1], 0.f);

    for (int k0 = 0; k0 < 64; k0 += 32) {
#pragma unroll
        for (int it = 0; it < 2; it++) {
            int i = tid + it * 256;
            int r = i >> 3, c4 = i & 7;
            float4 v = *(const float4*)(A + (size_t)(rowBase + r) * 64 + k0 + c4 * 4);
            float* ph = Ah + r * 40 + c4 * 4;
            float* pl = Al + r * 40 + c4 * 4;
            split_tf32(v.x, ph[0], pl[0]); split_tf32(v.y, ph[1], pl[1]);
            split_tf32(v.z, ph[2], pl[2]); split_tf32(v.w, ph[3], pl[3]);
        }
        for (int i = tid; i < 2048; i += 256) {
            int r = i >> 6, c = i & 63;
            float f = (c < 32) ? W2[(size_t)(k0 + r) * 32 + c]
                               : Wl[(size_t)(128 + k0 + r) * 32 + (c - 32)];
            split_tf32(f, Bh[r * 72 + c], Bl[r * 72 + c]);
        }
        __syncthreads();
#pragma unroll
        for (int kk = 0; kk < 32; kk += 8) {
            FragA ah, al;
            wmma::load_matrix_sync(ah, Ah + wm * 16 * 40 + kk, 40);
            wmma::load_matrix_sync(al, Al + wm * 16 * 40 + kk, 40);
#pragma unroll
            for (int t = 0; t < 2; t++) {
                int nt = wn * 2 + t;
                FragB bh, bl;
                wmma::load_matrix_sync(bh, Bh + kk * 72 + nt * 16, 72);
                wmma::load_matrix_sync(bl, Bl + kk * 72 + nt * 16, 72);
                mma3(acc[t], ah, al, bh, bl);
            }
        }
        __syncthreads();
    }
    int gr0 = rowBase + wm * 16;
#pragma unroll
    for (int t = 0; t < 2; t++) {
        int nt = wn * 2 + t;
        if (nt < 2) {
            wmma::store_matrix_sync(T2 + (size_t)gr0 * 32 + nt * 16, acc[t], 32, wmma::mem_row_major);
        } else {
            float* p = L + (size_t)gr0 * 32 + (nt - 2) * 16;
            FragC c0;
            wmma::load_matrix_sync(c0, p, 32, wmma::mem_row_major);
#pragma unroll
            for (int i = 0; i < c0.num_elements; i++) acc[t].x[i] += c0.x[i];
            wmma::store_matrix_sync(p, acc[t], 32, wmma::mem_row_major);
        }
    }
}

// ---------------------------------------------------------------- GEMM3: logits += (h2agg + t2*dinv^2 + b2) @ Wl2
// block 64x32, K=32 single chunk, 8 warps 1 tile each
__global__ __launch_bounds__(256) void k_gemm3_tc(
    const float* __restrict__ AGG, const float* __restrict__ T2,
    const float* __restrict__ dinv, const float* __restrict__ b2,
    const float* __restrict__ Wl2, float* __restrict__ L) {
    __shared__ float Ah[64 * 40], Al[64 * 40];
    __shared__ float Bh[32 * 40], Bl[32 * 40];
    int tid = threadIdx.x;
    int warp = tid >> 5;
    int wm = warp & 3, wn = warp >> 2;
    int rowBase = blockIdx.x * 64;

#pragma unroll
    for (int it = 0; it < 2; it++) {
        int i = tid + it * 256;
        int r = i >> 3, c4 = i & 7;
        int gr = rowBase + r;
        float di = dinv[gr]; float d2 = di * di;
        float4 ag = *(const float4*)(AGG + (size_t)gr * 32 + c4 * 4);
        float4 tv = *(const float4*)(T2  + (size_t)gr * 32 + c4 * 4);
        float4 bv = *(const float4*)(b2 + c4 * 4);
        float* ph = Ah + r * 40 + c4 * 4;
        float* pl = Al + r * 40 + c4 * 4;
        split_tf32(ag.x + tv.x * d2 + bv.x, ph[0], pl[0]);
        split_tf32(ag.y + tv.y * d2 + bv.y, ph[1], pl[1]);
        split_tf32(ag.z + tv.z * d2 + bv.z, ph[2], pl[2]);
        split_tf32(ag.w + tv.w * d2 + bv.w, ph[3], pl[3]);
    }
    for (int i = tid; i < 1024; i += 256) {
        int r = i >> 5, c = i & 31;
        split_tf32(Wl2[i], Bh[r * 40 + c], Bl[r * 40 + c]);
    }
    __syncthreads();

    FragC acc;
    wmma::fill_fragment(acc, 0.f);
#pragma unroll
    for (int kk = 0; kk < 32; kk += 8) {
        FragA ah, al;
        wmma::load_matrix_sync(ah, Ah + wm * 16 * 40 + kk, 40);
        wmma::load_matrix_sync(al, Al + wm * 16 * 40 + kk, 40);
        FragB bh, bl;
        wmma::load_matrix_sync(bh, Bh + kk * 40 + wn * 16, 40);
        wmma::load_matrix_sync(bl, Bl + kk * 40 + wn * 16, 40);
        mma3(acc, ah, al, bh, bl);
    }
    float* p = L + (size_t)(rowBase + wm * 16) * 32 + wn * 16;
    FragC c0;
    wmma::load_matrix_sync(c0, p, 32, wmma::mem_row_major);
#pragma unroll
    for (int i = 0; i < c0.num_elements; i++) acc.x[i] += c0.x[i];
    wmma::store_matrix_sync(p, acc, 32, wmma::mem_row_major);
}

// ---------------------------------------------------------------- edge scatter (RED v4)
template<int C4>
__global__ void k_scatter(const int* __restrict__ ei, const float* __restrict__ norm,
                          const float* __restrict__ h, float* __restrict__ agg, int E) {
    int idx = blockIdx.x * blockDim.x + threadIdx.x;
    if (idx >= E * C4) return;
    int e = idx / C4;
    int q = idx - e * C4;
    int s = ei[e];
    int d = ei[E + e];
    float nrm = norm[e];
    float4 hv = reinterpret_cast<const float4*>(h)[(size_t)s * C4 + q];
    float4* p = reinterpret_cast<float4*>(agg) + (size_t)d * C4 + q;
    asm volatile("red.global.add.v4.f32 [%0], {%1, %2, %3, %4};"
                 :: "l"(p), "f"(hv.x * nrm), "f"(hv.y * nrm),
                    "f"(hv.z * nrm), "f"(hv.w * nrm)
                 : "memory");
}

// ---------------------------------------------------------------- epi1: h1 = relu(h1agg + h*dinv^2 + b1)
__global__ void k_epi1(float* __restrict__ h1, const float* __restrict__ h,
                       const float* __restrict__ dinv, const float* __restrict__ b1, int N) {
    int idx = blockIdx.x * blockDim.x + threadIdx.x;   // over N*16 float4
    if (idx >= N * 16) return;
    int node = idx >> 4;
    int c4 = idx & 15;
    float di = dinv[node]; float d2 = di * di;
    float4 ag = *(float4*)(h1 + (size_t)idx * 4);
    float4 hv = *(const float4*)(h + (size_t)idx * 4);
    float4 bv = *(const float4*)(b1 + c4 * 4);
    *(float4*)(h1 + (size_t)idx * 4) =
        make_float4(fmaxf(ag.x + hv.x * d2 + bv.x, 0.f),
                    fmaxf(ag.y + hv.y * d2 + bv.y, 0.f),
                    fmaxf(ag.z + hv.z * d2 + bv.z, 0.f),
                    fmaxf(ag.w + hv.w * d2 + bv.w, 0.f));
}

// ---------------------------------------------------------------- log_softmax
__global__ void k_lsm(const float* __restrict__ logits, const float* __restrict__ bl,
                      float* __restrict__ out, int N) {
    int node = blockIdx.x * 8 + (threadIdx.x >> 5);
    int lane = threadIdx.x & 31;
    if (node >= N) return;
    float v = logits[(size_t)node * 32 + lane] + bl[lane];
    float m = v;
#pragma unroll
    for (int o = 16; o > 0; o >>= 1) m = fmaxf(m, __shfl_xor_sync(0xffffffffu, m, o));
    float ex = expf(v - m);
    float s = ex;
#pragma unroll
    for (int o = 16; o > 0; o >>= 1) s += __shfl_xor_sync(0xffffffffu, s, o);
    out[(size_t)node * 32 + lane] = v - m - logf(s);
}

// ----------------------------------------------------------------
extern "C" void kernel_launch(void* const* d_in, const int* in_sizes, int n_in,
                              void* d_out, int out_size) {
    const float* x  = (const float*)d_in[0];
    const int*   ei = (const int*)d_in[1];
    const float* W1 = (const float*)d_in[2];
    const float* b1 = (const float*)d_in[3];
    const float* W2 = (const float*)d_in[4];
    const float* b2 = (const float*)d_in[5];
    const float* Wl = (const float*)d_in[6];
    const float* bl = (const float*)d_in[7];
    float*       out = (float*)d_out;

    int M = in_sizes[0] / 128;   // 100000
    int E = in_sizes[1] / 2;     // 1600000

    float* s = nullptr;
    cudaGetSymbolAddress((void**)&s, g_scratch);
    float* dinv   = s;
    float* h1     = dinv + NP;
    float* h2agg  = h1 + (size_t)NP * 64;
    float* h      = h2agg + (size_t)NP * 32;
    float* t2     = h + (size_t)NP * 64;
    float* logits = t2 + (size_t)NP * 32;
    float* norm   = logits + (size_t)NP * 32;

    // zero dinv + h1 + h2agg (contiguous NP*97 floats; includes pad rows)
    k_zero<<<2048, THREADS>>>((float4*)dinv, NP * 97 / 4);

    k_deg<<<(E + THREADS - 1) / THREADS, THREADS>>>(ei, dinv, E);
    k_dinv<<<(M + THREADS - 1) / THREADS, THREADS>>>(dinv, M);
    k_norm<<<(E + THREADS - 1) / THREADS, THREADS>>>(ei, dinv, norm, E);

    int gb = NP / 64;            // 1563
    int gw = (M + 7) / 8;

    // layer 1 (+ x@Wl0)
    k_gemm1_tc<<<gb, 256>>>(x, W1, Wl, h, logits, M);
    k_scatter<16><<<(E * 16 + THREADS - 1) / THREADS, THREADS>>>(ei, norm, h, h1, E);
    k_epi1<<<(M * 16 + THREADS - 1) / THREADS, THREADS>>>(h1, h, dinv, b1, M);

    // layer 2 (+ h1@Wl1)
    k_gemm2_tc<<<gb, 256>>>(h1, W2, Wl, t2, logits);
    k_scatter<8><<<(E * 8 + THREADS - 1) / THREADS, THREADS>>>(ei, norm, t2, h2agg, E);

    // final: epilogue-fused h2 @ Wl2
    k_gemm3_tc<<<gb, 256>>>(h2agg, t2, dinv, b2, Wl + 192 * 32, logits);

    // log_softmax
    k_lsm<<<gw, THREADS>>>(logits, bl, out, M);
}

// round 14
// speedup vs baseline: 1.3110x; 1.2077x over previous
#include <cuda_runtime.h>

#define N_NODES 100000
#define NP      100096   // 782 * 128
#define THREADS 256
#define E_EDGES 1600000

// floats: dinv[NP] | h1agg[64NP] | h2agg[32NP] | h[64NP] | t2[32NP] | logits[32NP]
__device__ float g_scratch[(size_t)NP * 225];

// ---------------------------------------------------------------- zero (dinv+h1agg+h2agg = 97*NP floats)
__global__ void k_zero(float4* __restrict__ p, int n4) {
    int i = blockIdx.x * blockDim.x + threadIdx.x;
    int stride = gridDim.x * blockDim.x;
    float4 z = make_float4(0.f, 0.f, 0.f, 0.f);
    for (; i < n4; i += stride) p[i] = z;
}

// ---------------------------------------------------------------- degree (float RED into dinv buffer)
__global__ void k_deg(const int* __restrict__ ei, float* __restrict__ deg, int E) {
    int e = blockIdx.x * blockDim.x + threadIdx.x;
    if (e >= E) return;
    asm volatile("red.global.add.f32 [%0], %1;" :: "l"(deg + ei[E + e]), "f"(1.0f) : "memory");
}

__global__ void k_dinv(float* __restrict__ dinv, int N) {
    int i = blockIdx.x * blockDim.x + threadIdx.x;
    if (i < N) dinv[i] = rsqrtf(dinv[i] + 1.0f);
}

// ---------------------------------------------------------------- GEMM1: [h | logits] = x @ [W1 | Wl0]
// BM=128, BN=96, BK=16, 384 threads, TM=8, TN=4
__global__ __launch_bounds__(384) void k_gemm_f1(
    const float* __restrict__ A, const float* __restrict__ W1, const float* __restrict__ Wl,
    float* __restrict__ H, float* __restrict__ L, int M) {
    __shared__ float As[16][132];
    __shared__ float Bs[16][96];
    int tid = threadIdx.x;
    int tr = tid / 24, tc = tid % 24;
    int rowBase = blockIdx.x * 128;
    float acc[8][4];
#pragma unroll
    for (int i = 0; i < 8; i++)
#pragma unroll
        for (int j = 0; j < 4; j++) acc[i][j] = 0.f;

    for (int k0 = 0; k0 < 128; k0 += 16) {
        for (int i = tid; i < 512; i += 384) {
            int r = i >> 2, c4 = i & 3;
            int gr = rowBase + r;
            float4 v = (gr < M) ? *(const float4*)(A + (size_t)gr * 128 + k0 + c4 * 4)
                                : make_float4(0.f, 0.f, 0.f, 0.f);
            As[c4 * 4 + 0][r] = v.x; As[c4 * 4 + 1][r] = v.y;
            As[c4 * 4 + 2][r] = v.z; As[c4 * 4 + 3][r] = v.w;
        }
        for (int i = tid; i < 1536; i += 384) {
            int r = i / 96, c = i % 96;
            Bs[r][c] = (c < 64) ? W1[(size_t)(k0 + r) * 64 + c]
                                : Wl[(size_t)(k0 + r) * 32 + (c - 64)];
        }
        __syncthreads();
#pragma unroll
        for (int kk = 0; kk < 16; kk++) {
            float4 a0 = *(const float4*)&As[kk][tr * 8];
            float4 a1 = *(const float4*)&As[kk][tr * 8 + 4];
            float4 bv = *(const float4*)&Bs[kk][tc * 4];
            float a[8] = {a0.x, a0.y, a0.z, a0.w, a1.x, a1.y, a1.z, a1.w};
            float b[4] = {bv.x, bv.y, bv.z, bv.w};
#pragma unroll
            for (int i = 0; i < 8; i++)
#pragma unroll
                for (int j = 0; j < 4; j++) acc[i][j] += a[i] * b[j];
        }
        __syncthreads();
    }
#pragma unroll
    for (int i = 0; i < 8; i++) {
        int gr = rowBase + tr * 8 + i;    // < NP always, buffers padded
        float4 v = make_float4(acc[i][0], acc[i][1], acc[i][2], acc[i][3]);
        if (tc < 16) *(float4*)(H + (size_t)gr * 64 + tc * 4) = v;
        else         *(float4*)(L + (size_t)gr * 32 + (tc - 16) * 4) = v;
    }
}

// ---------------------------------------------------------------- GEMM2 (epi1 fused in A-load):
// A_eff = relu(h1agg + h*dinv^2 + b1);  [t2 | logits+=] = A_eff @ [W2 | Wl1]
__global__ __launch_bounds__(256) void k_gemm_f2(
    const float* __restrict__ AGG, const float* __restrict__ H,
    const float* __restrict__ dinv, const float* __restrict__ b1,
    const float* __restrict__ W2, const float* __restrict__ Wl,
    float* __restrict__ T2, float* __restrict__ L) {
    __shared__ float As[16][132];
    __shared__ float Bs[16][64];
    int tid = threadIdx.x;
    int tr = tid / 16, tc = tid % 16;
    int rowBase = blockIdx.x * 128;
    float acc[8][4];
#pragma unroll
    for (int i = 0; i < 8; i++)
#pragma unroll
        for (int j = 0; j < 4; j++) acc[i][j] = 0.f;

    for (int k0 = 0; k0 < 64; k0 += 16) {
        for (int i = tid; i < 512; i += 256) {
            int r = i >> 2, c4 = i & 3;
            int gr = rowBase + r;
            float di = dinv[gr]; float d2 = di * di;
            float4 ag = *(const float4*)(AGG + (size_t)gr * 64 + k0 + c4 * 4);
            float4 hv = *(const float4*)(H   + (size_t)gr * 64 + k0 + c4 * 4);
            float4 bv = *(const float4*)(b1 + k0 + c4 * 4);
            As[c4 * 4 + 0][r] = fmaxf(ag.x + hv.x * d2 + bv.x, 0.f);
            As[c4 * 4 + 1][r] = fmaxf(ag.y + hv.y * d2 + bv.y, 0.f);
            As[c4 * 4 + 2][r] = fmaxf(ag.z + hv.z * d2 + bv.z, 0.f);
            As[c4 * 4 + 3][r] = fmaxf(ag.w + hv.w * d2 + bv.w, 0.f);
        }
        for (int i = tid; i < 1024; i += 256) {
            int r = i / 64, c = i % 64;
            Bs[r][c] = (c < 32) ? W2[(size_t)(k0 + r) * 32 + c]
                                : Wl[(size_t)(128 + k0 + r) * 32 + (c - 32)];
        }
        __syncthreads();
#pragma unroll
        for (int kk = 0; kk < 16; kk++) {
            float4 a0 = *(const float4*)&As[kk][tr * 8];
            float4 a1 = *(const float4*)&As[kk][tr * 8 + 4];
            float4 bv = *(const float4*)&Bs[kk][tc * 4];
            float a[8] = {a0.x, a0.y, a0.z, a0.w, a1.x, a1.y, a1.z, a1.w};
            float b[4] = {bv.x, bv.y, bv.z, bv.w};
#pragma unroll
            for (int i = 0; i < 8; i++)
#pragma unroll
                for (int j = 0; j < 4; j++) acc[i][j] += a[i] * b[j];
        }
        __syncthreads();
    }
#pragma unroll
    for (int i = 0; i < 8; i++) {
        int gr = rowBase + tr * 8 + i;
        if (tc < 8) {
            *(float4*)(T2 + (size_t)gr * 32 + tc * 4) =
                make_float4(acc[i][0], acc[i][1], acc[i][2], acc[i][3]);
        } else {
            float* p = L + (size_t)gr * 32 + (tc - 8) * 4;
            float4 old = *(float4*)p;
            *(float4*)p = make_float4(old.x + acc[i][0], old.y + acc[i][1],
                                      old.z + acc[i][2], old.w + acc[i][3]);
        }
    }
}

// ---------------------------------------------------------------- GEMM3 (+ log_softmax epilogue -> out):
// out = log_softmax(logits + (h2agg + t2*dinv^2 + b2) @ Wl2 + bl)
__global__ __launch_bounds__(128) void k_gemm_f3(
    const float* __restrict__ AGG, const float* __restrict__ T2,
    const float* __restrict__ dinv, const float* __restrict__ b2,
    const float* __restrict__ Wl2, const float* __restrict__ L,
    const float* __restrict__ bl, float* __restrict__ out, int M) {
    __shared__ float As[32][132];
    __shared__ float Bs[32][32];
    int tid = threadIdx.x;
    int tr = tid / 8, tc = tid % 8;
    int rowBase = blockIdx.x * 128;

    for (int i = tid; i < 1024; i += 128) {
        int r = i >> 3, c4 = i & 7;
        int gr = rowBase + r;
        float di = dinv[gr]; float d2 = di * di;
        float4 ag = *(const float4*)(AGG + (size_t)gr * 32 + c4 * 4);
        float4 tv = *(const float4*)(T2  + (size_t)gr * 32 + c4 * 4);
        float4 bv = *(const float4*)(b2 + c4 * 4);
        As[c4 * 4 + 0][r] = ag.x + tv.x * d2 + bv.x;
        As[c4 * 4 + 1][r] = ag.y + tv.y * d2 + bv.y;
        As[c4 * 4 + 2][r] = ag.z + tv.z * d2 + bv.z;
        As[c4 * 4 + 3][r] = ag.w + tv.w * d2 + bv.w;
    }
    for (int i = tid; i < 1024; i += 128) Bs[i >> 5][i & 31] = Wl2[i];
    __syncthreads();

    float acc[8][4];
#pragma unroll
    for (int i = 0; i < 8; i++)
#pragma unroll
        for (int j = 0; j < 4; j++) acc[i][j] = 0.f;
#pragma unroll
    for (int kk = 0; kk < 32; kk++) {
        float4 a0 = *(const float4*)&As[kk][tr * 8];
        float4 a1 = *(const float4*)&As[kk][tr * 8 + 4];
        float4 bv = *(const float4*)&Bs[kk][tc * 4];
        float a[8] = {a0.x, a0.y, a0.z, a0.w, a1.x, a1.y, a1.z, a1.w};
        float b[4] = {bv.x, bv.y, bv.z, bv.w};
#pragma unroll
        for (int i = 0; i < 8; i++)
#pragma unroll
            for (int j = 0; j < 4; j++) acc[i][j] += a[i] * b[j];
    }

    float4 blv = *(const float4*)(bl + tc * 4);
#pragma unroll
    for (int i = 0; i < 8; i++) {
        int gr = rowBase + tr * 8 + i;
        float4 old = *(const float4*)(L + (size_t)gr * 32 + tc * 4);
        float v0 = acc[i][0] + old.x + blv.x;
        float v1 = acc[i][1] + old.y + blv.y;
        float v2 = acc[i][2] + old.z + blv.z;
        float v3 = acc[i][3] + old.w + blv.w;
        // log_softmax across the row (8 lanes x 4 cols, lanes tc=0..7 are consecutive)
        float m = fmaxf(fmaxf(v0, v1), fmaxf(v2, v3));
#pragma unroll
        for (int o = 1; o < 8; o <<= 1) m = fmaxf(m, __shfl_xor_sync(0xffffffffu, m, o, 8));
        float s = expf(v0 - m) + expf(v1 - m) + expf(v2 - m) + expf(v3 - m);
#pragma unroll
        for (int o = 1; o < 8; o <<= 1) s += __shfl_xor_sync(0xffffffffu, s, o, 8);
        float ml = m + logf(s);
        if (gr < M)
            *(float4*)(out + (size_t)gr * 32 + tc * 4) =
                make_float4(v0 - ml, v1 - ml, v2 - ml, v3 - ml);
    }
}

// ---------------------------------------------------------------- edge scatter (RED v4), leader-lane index+norm broadcast
// C4 = float4s per row (16 or 8). E*C4 must be a multiple of 256 (it is: E=1.6M).
template<int C4>
__global__ void k_scatter(const int* __restrict__ ei, const float* __restrict__ dinv,
                          const float* __restrict__ h, float* __restrict__ agg, int E) {
    int idx = blockIdx.x * blockDim.x + threadIdx.x;
    int lane = threadIdx.x & 31;
    int e = idx / C4;
    int q = idx & (C4 - 1);
    int s = 0, d = 0;
    float nrm = 0.f;
    if ((lane & (C4 - 1)) == 0) {      // segment leader
        s = ei[e];
        d = ei[E + e];
        nrm = dinv[s] * dinv[d];
    }
    int src = lane & ~(C4 - 1);
    s   = __shfl_sync(0xffffffffu, s,   src);
    d   = __shfl_sync(0xffffffffu, d,   src);
    nrm = __shfl_sync(0xffffffffu, nrm, src);
    float4 hv = reinterpret_cast<const float4*>(h)[(size_t)s * C4 + q];
    float4* p = reinterpret_cast<float4*>(agg) + (size_t)d * C4 + q;
    asm volatile("red.global.add.v4.f32 [%0], {%1, %2, %3, %4};"
                 :: "l"(p), "f"(hv.x * nrm), "f"(hv.y * nrm),
                    "f"(hv.z * nrm), "f"(hv.w * nrm)
                 : "memory");
}

// ----------------------------------------------------------------
extern "C" void kernel_launch(void* const* d_in, const int* in_sizes, int n_in,
                              void* d_out, int out_size) {
    const float* x  = (const float*)d_in[0];
    const int*   ei = (const int*)d_in[1];
    const float* W1 = (const float*)d_in[2];
    const float* b1 = (const float*)d_in[3];
    const float* W2 = (const float*)d_in[4];
    const float* b2 = (const float*)d_in[5];
    const float* Wl = (const float*)d_in[6];
    const float* bl = (const float*)d_in[7];
    float*       out = (float*)d_out;

    int M = in_sizes[0] / 128;   // 100000
    int E = in_sizes[1] / 2;     // 1600000

    float* s = nullptr;
    cudaGetSymbolAddress((void**)&s, g_scratch);
    float* dinv   = s;
    float* h1agg  = dinv + NP;
    float* h2agg  = h1agg + (size_t)NP * 64;
    float* h      = h2agg + (size_t)NP * 32;
    float* t2     = h + (size_t)NP * 64;
    float* logits = t2 + (size_t)NP * 32;

    // zero dinv + h1agg + h2agg (contiguous 97*NP floats)
    k_zero<<<2048, THREADS>>>((float4*)dinv, NP * 97 / 4);

    k_deg<<<(E + THREADS - 1) / THREADS, THREADS>>>(ei, dinv, E);
    k_dinv<<<(M + THREADS - 1) / THREADS, THREADS>>>(dinv, M);

    int gb = NP / 128;           // 782

    // layer 1 (+ x@Wl0)
    k_gemm_f1<<<gb, 384>>>(x, W1, Wl, h, logits, M);
    k_scatter<16><<<E * 16 / THREADS, THREADS>>>(ei, dinv, h, h1agg, E);

    // layer 2 (+ h1@Wl1), epi1 fused into A-load
    k_gemm_f2<<<gb, 256>>>(h1agg, h, dinv, b1, W2, Wl, t2, logits);
    k_scatter<8><<<E * 8 / THREADS, THREADS>>>(ei, dinv, t2, h2agg, E);

    // final: epilogue-fused h2 @ Wl2 + bias + log_softmax -> out
    k_gemm_f3<<<gb, 128>>>(h2agg, t2, dinv, b2, Wl + 192 * 32, logits, bl, out, M);
}

// round 15
// speedup vs baseline: 1.3914x; 1.0613x over previous
#include <cuda_runtime.h>

#define N_NODES 100000
#define NP      100096   // 782 * 128
#define THREADS 256
#define E_EDGES 1600000

// floats: dinv[NP] | h1agg[64NP] | h2agg[32NP] | h[64NP] | t2[32NP] | logits[32NP]
__device__ float g_scratch[(size_t)NP * 225];

// ---------------------------------------------------------------- zero
__global__ void k_zero(float4* __restrict__ p, int n4) {
    int i = blockIdx.x * blockDim.x + threadIdx.x;
    int stride = gridDim.x * blockDim.x;
    float4 z = make_float4(0.f, 0.f, 0.f, 0.f);
    for (; i < n4; i += stride) p[i] = z;
}

// ---------------------------------------------------------------- degree (float RED into dinv buffer)
__global__ void k_deg(const int* __restrict__ ei, float* __restrict__ deg, int E) {
    int e = blockIdx.x * blockDim.x + threadIdx.x;
    if (e >= E) return;
    asm volatile("red.global.add.f32 [%0], %1;" :: "l"(deg + ei[E + e]), "f"(1.0f) : "memory");
}

__global__ void k_dinv(float* __restrict__ dinv, int N) {
    int i = blockIdx.x * blockDim.x + threadIdx.x;
    if (i < N) dinv[i] = rsqrtf(dinv[i] + 1.0f);
}

// ---------------------------------------------------------------- GEMM1: [h | logits] = x @ [W1 | Wl0]
// BM=128, BN=96 (cols: 64 H + 32 L), BK=16, 256 threads, TM=8, TN=4+2, double-buffered
__global__ __launch_bounds__(256) void k_gemm_f1(
    const float* __restrict__ A, const float* __restrict__ W1, const float* __restrict__ Wl,
    float* __restrict__ H, float* __restrict__ L, int M) {
    __shared__ float As[2][16][132];
    __shared__ float Bs[2][16][96];
    int tid = threadIdx.x;
    int tr = tid >> 4, tc = tid & 15;
    int rowBase = blockIdx.x * 128;

    float acc[8][6];
#pragma unroll
    for (int i = 0; i < 8; i++)
#pragma unroll
        for (int j = 0; j < 6; j++) acc[i][j] = 0.f;

    // prologue: chunk 0 -> smem[0]
#pragma unroll
    for (int t = 0; t < 2; t++) {
        int i = tid + t * 256;
        int r = i >> 2, c4 = i & 3;
        int gr = rowBase + r;
        float4 v = (gr < M) ? *(const float4*)(A + (size_t)gr * 128 + c4 * 4)
                            : make_float4(0.f, 0.f, 0.f, 0.f);
        As[0][c4 * 4 + 0][r] = v.x; As[0][c4 * 4 + 1][r] = v.y;
        As[0][c4 * 4 + 2][r] = v.z; As[0][c4 * 4 + 3][r] = v.w;
    }
#pragma unroll
    for (int t = 0; t < 6; t++) {
        int i = tid + t * 256;
        int r = i / 96, c = i - r * 96;
        Bs[0][r][c] = (c < 64) ? W1[(size_t)r * 64 + c] : Wl[(size_t)r * 32 + (c - 64)];
    }
    __syncthreads();

    float4 rA[2];
    float rB[6];
    for (int k0 = 0; k0 < 128; k0 += 16) {
        int buf = (k0 >> 4) & 1;
        bool more = (k0 < 112);
        if (more) {
#pragma unroll
            for (int t = 0; t < 2; t++) {
                int i = tid + t * 256;
                int r = i >> 2, c4 = i & 3;
                int gr = rowBase + r;
                rA[t] = (gr < M) ? *(const float4*)(A + (size_t)gr * 128 + (k0 + 16) + c4 * 4)
                                 : make_float4(0.f, 0.f, 0.f, 0.f);
            }
#pragma unroll
            for (int t = 0; t < 6; t++) {
                int i = tid + t * 256;
                int r = i / 96, c = i - r * 96;
                rB[t] = (c < 64) ? W1[(size_t)(k0 + 16 + r) * 64 + c]
                                 : Wl[(size_t)(k0 + 16 + r) * 32 + (c - 64)];
            }
        }
#pragma unroll
        for (int kk = 0; kk < 16; kk++) {
            float4 a0 = *(const float4*)&As[buf][kk][tr * 8];
            float4 a1 = *(const float4*)&As[buf][kk][tr * 8 + 4];
            float4 b0 = *(const float4*)&Bs[buf][kk][tc * 4];
            float2 b1 = *(const float2*)&Bs[buf][kk][64 + tc * 2];
            float a[8] = {a0.x, a0.y, a0.z, a0.w, a1.x, a1.y, a1.z, a1.w};
            float b[6] = {b0.x, b0.y, b0.z, b0.w, b1.x, b1.y};
#pragma unroll
            for (int i = 0; i < 8; i++)
#pragma unroll
                for (int j = 0; j < 6; j++) acc[i][j] += a[i] * b[j];
        }
        if (more) {
            int nb = buf ^ 1;
#pragma unroll
            for (int t = 0; t < 2; t++) {
                int i = tid + t * 256;
                int r = i >> 2, c4 = i & 3;
                As[nb][c4 * 4 + 0][r] = rA[t].x; As[nb][c4 * 4 + 1][r] = rA[t].y;
                As[nb][c4 * 4 + 2][r] = rA[t].z; As[nb][c4 * 4 + 3][r] = rA[t].w;
            }
#pragma unroll
            for (int t = 0; t < 6; t++) {
                int i = tid + t * 256;
                int r = i / 96, c = i - r * 96;
                Bs[nb][r][c] = rB[t];
            }
            __syncthreads();
        }
    }
#pragma unroll
    for (int i = 0; i < 8; i++) {
        int gr = rowBase + tr * 8 + i;   // < NP, scratch padded
        *(float4*)(H + (size_t)gr * 64 + tc * 4) =
            make_float4(acc[i][0], acc[i][1], acc[i][2], acc[i][3]);
        *(float2*)(L + (size_t)gr * 32 + tc * 2) = make_float2(acc[i][4], acc[i][5]);
    }
}

// ---------------------------------------------------------------- GEMM2 (epi1 fused in A-load), double-buffered:
// A_eff = relu(h1agg + h*dinv^2 + b1);  [t2 | logits+=] = A_eff @ [W2 | Wl1]
__global__ __launch_bounds__(256) void k_gemm_f2(
    const float* __restrict__ AGG, const float* __restrict__ H,
    const float* __restrict__ dinv, const float* __restrict__ b1,
    const float* __restrict__ W2, const float* __restrict__ Wl,
    float* __restrict__ T2, float* __restrict__ L) {
    __shared__ float As[2][16][132];
    __shared__ float Bs[2][16][64];
    int tid = threadIdx.x;
    int tr = tid >> 4, tc = tid & 15;
    int rowBase = blockIdx.x * 128;

    float acc[8][4];
#pragma unroll
    for (int i = 0; i < 8; i++)
#pragma unroll
        for (int j = 0; j < 4; j++) acc[i][j] = 0.f;

    // prologue chunk 0
#pragma unroll
    for (int t = 0; t < 2; t++) {
        int i = tid + t * 256;
        int r = i >> 2, c4 = i & 3;
        int gr = rowBase + r;
        float di = dinv[gr]; float d2 = di * di;
        float4 ag = *(const float4*)(AGG + (size_t)gr * 64 + c4 * 4);
        float4 hv = *(const float4*)(H   + (size_t)gr * 64 + c4 * 4);
        float4 bv = *(const float4*)(b1 + c4 * 4);
        As[0][c4 * 4 + 0][r] = fmaxf(ag.x + hv.x * d2 + bv.x, 0.f);
        As[0][c4 * 4 + 1][r] = fmaxf(ag.y + hv.y * d2 + bv.y, 0.f);
        As[0][c4 * 4 + 2][r] = fmaxf(ag.z + hv.z * d2 + bv.z, 0.f);
        As[0][c4 * 4 + 3][r] = fmaxf(ag.w + hv.w * d2 + bv.w, 0.f);
    }
#pragma unroll
    for (int t = 0; t < 4; t++) {
        int i = tid + t * 256;
        int r = i >> 6, c = i & 63;
        Bs[0][r][c] = (c < 32) ? W2[(size_t)r * 32 + c] : Wl[(size_t)(128 + r) * 32 + (c - 32)];
    }
    __syncthreads();

    float4 rAG[2], rH[2];
    float rd2[2], rB[4];
    for (int k0 = 0; k0 < 64; k0 += 16) {
        int buf = (k0 >> 4) & 1;
        bool more = (k0 < 48);
        if (more) {
#pragma unroll
            for (int t = 0; t < 2; t++) {
                int i = tid + t * 256;
                int r = i >> 2, c4 = i & 3;
                int gr = rowBase + r;
                float di = dinv[gr];
                rd2[t] = di * di;
                rAG[t] = *(const float4*)(AGG + (size_t)gr * 64 + (k0 + 16) + c4 * 4);
                rH[t]  = *(const float4*)(H   + (size_t)gr * 64 + (k0 + 16) + c4 * 4);
            }
#pragma unroll
            for (int t = 0; t < 4; t++) {
                int i = tid + t * 256;
                int r = i >> 6, c = i & 63;
                rB[t] = (c < 32) ? W2[(size_t)(k0 + 16 + r) * 32 + c]
                                 : Wl[(size_t)(128 + k0 + 16 + r) * 32 + (c - 32)];
            }
        }
#pragma unroll
        for (int kk = 0; kk < 16; kk++) {
            float4 a0 = *(const float4*)&As[buf][kk][tr * 8];
            float4 a1 = *(const float4*)&As[buf][kk][tr * 8 + 4];
            float4 bv = *(const float4*)&Bs[buf][kk][tc * 4];
            float a[8] = {a0.x, a0.y, a0.z, a0.w, a1.x, a1.y, a1.z, a1.w};
            float b[4] = {bv.x, bv.y, bv.z, bv.w};
#pragma unroll
            for (int i = 0; i < 8; i++)
#pragma unroll
                for (int j = 0; j < 4; j++) acc[i][j] += a[i] * b[j];
        }
        if (more) {
            int nb = buf ^ 1;
#pragma unroll
            for (int t = 0; t < 2; t++) {
                int i = tid + t * 256;
                int r = i >> 2, c4 = i & 3;
                float4 bv = *(const float4*)(b1 + (k0 + 16) + c4 * 4);
                As[nb][c4 * 4 + 0][r] = fmaxf(rAG[t].x + rH[t].x * rd2[t] + bv.x, 0.f);
                As[nb][c4 * 4 + 1][r] = fmaxf(rAG[t].y + rH[t].y * rd2[t] + bv.y, 0.f);
                As[nb][c4 * 4 + 2][r] = fmaxf(rAG[t].z + rH[t].z * rd2[t] + bv.z, 0.f);
                As[nb][c4 * 4 + 3][r] = fmaxf(rAG[t].w + rH[t].w * rd2[t] + bv.w, 0.f);
            }
#pragma unroll
            for (int t = 0; t < 4; t++) {
                int i = tid + t * 256;
                int r = i >> 6, c = i & 63;
                Bs[nb][r][c] = rB[t];
            }
            __syncthreads();
        }
    }
#pragma unroll
    for (int i = 0; i < 8; i++) {
        int gr = rowBase + tr * 8 + i;
        if (tc < 8) {
            *(float4*)(T2 + (size_t)gr * 32 + tc * 4) =
                make_float4(acc[i][0], acc[i][1], acc[i][2], acc[i][3]);
        } else {
            float* p = L + (size_t)gr * 32 + (tc - 8) * 4;
            float4 old = *(float4*)p;
            *(float4*)p = make_float4(old.x + acc[i][0], old.y + acc[i][1],
                                      old.z + acc[i][2], old.w + acc[i][3]);
        }
    }
}

// ---------------------------------------------------------------- GEMM3 (+ log_softmax epilogue -> out)
__global__ __launch_bounds__(128) void k_gemm_f3(
    const float* __restrict__ AGG, const float* __restrict__ T2,
    const float* __restrict__ dinv, const float* __restrict__ b2,
    const float* __restrict__ Wl2, const float* __restrict__ L,
    const float* __restrict__ bl, float* __restrict__ out, int M) {
    __shared__ float As[32][132];
    __shared__ float Bs[32][32];
    int tid = threadIdx.x;
    int tr = tid / 8, tc = tid % 8;
    int rowBase = blockIdx.x * 128;

    for (int i = tid; i < 1024; i += 128) {
        int r = i >> 3, c4 = i & 7;
        int gr = rowBase + r;
        float di = dinv[gr]; float d2 = di * di;
        float4 ag = *(const float4*)(AGG + (size_t)gr * 32 + c4 * 4);
        float4 tv = *(const float4*)(T2  + (size_t)gr * 32 + c4 * 4);
        float4 bv = *(const float4*)(b2 + c4 * 4);
        As[c4 * 4 + 0][r] = ag.x + tv.x * d2 + bv.x;
        As[c4 * 4 + 1][r] = ag.y + tv.y * d2 + bv.y;
        As[c4 * 4 + 2][r] = ag.z + tv.z * d2 + bv.z;
        As[c4 * 4 + 3][r] = ag.w + tv.w * d2 + bv.w;
    }
    for (int i = tid; i < 1024; i += 128) Bs[i >> 5][i & 31] = Wl2[i];
    __syncthreads();

    float acc[8][4];
#pragma unroll
    for (int i = 0; i < 8; i++)
#pragma unroll
        for (int j = 0; j < 4; j++) acc[i][j] = 0.f;
#pragma unroll
    for (int kk = 0; kk < 32; kk++) {
        float4 a0 = *(const float4*)&As[kk][tr * 8];
        float4 a1 = *(const float4*)&As[kk][tr * 8 + 4];
        float4 bv = *(const float4*)&Bs[kk][tc * 4];
        float a[8] = {a0.x, a0.y, a0.z, a0.w, a1.x, a1.y, a1.z, a1.w};
        float b[4] = {bv.x, bv.y, bv.z, bv.w};
#pragma unroll
        for (int i = 0; i < 8; i++)
#pragma unroll
            for (int j = 0; j < 4; j++) acc[i][j] += a[i] * b[j];
    }

    float4 blv = *(const float4*)(bl + tc * 4);
#pragma unroll
    for (int i = 0; i < 8; i++) {
        int gr = rowBase + tr * 8 + i;
        float4 old = *(const float4*)(L + (size_t)gr * 32 + tc * 4);
        float v0 = acc[i][0] + old.x + blv.x;
        float v1 = acc[i][1] + old.y + blv.y;
        float v2 = acc[i][2] + old.z + blv.z;
        float v3 = acc[i][3] + old.w + blv.w;
        float m = fmaxf(fmaxf(v0, v1), fmaxf(v2, v3));
#pragma unroll
        for (int o = 1; o < 8; o <<= 1) m = fmaxf(m, __shfl_xor_sync(0xffffffffu, m, o, 8));
        float s = expf(v0 - m) + expf(v1 - m) + expf(v2 - m) + expf(v3 - m);
#pragma unroll
        for (int o = 1; o < 8; o <<= 1) s += __shfl_xor_sync(0xffffffffu, s, o, 8);
        float ml = m + logf(s);
        if (gr < M)
            *(float4*)(out + (size_t)gr * 32 + tc * 4) =
                make_float4(v0 - ml, v1 - ml, v2 - ml, v3 - ml);
    }
}

// ---------------------------------------------------------------- edge scatter: 2x RED.v4 per thread
// C4 = float4s per row (16 or 8). Group = C4/2 lanes per edge.
template<int C4>
__global__ void k_scatter(const int* __restrict__ ei, const float* __restrict__ dinv,
                          const float* __restrict__ h, float* __restrict__ agg, int E) {
    constexpr int G = C4 / 2;
    int idx = blockIdx.x * blockDim.x + threadIdx.x;
    int lane = threadIdx.x & 31;
    int e = idx / G;
    int q = idx & (G - 1);
    int s = 0, d = 0;
    float nrm = 0.f;
    if ((lane & (G - 1)) == 0) {
        s = ei[e];
        d = ei[E + e];
        nrm = dinv[s] * dinv[d];
    }
    int src = lane & ~(G - 1);
    s   = __shfl_sync(0xffffffffu, s,   src);
    d   = __shfl_sync(0xffffffffu, d,   src);
    nrm = __shfl_sync(0xffffffffu, nrm, src);
    const float4* hr = reinterpret_cast<const float4*>(h) + (size_t)s * C4;
    float4*       pr = reinterpret_cast<float4*>(agg) + (size_t)d * C4;
    float4 h0 = hr[q];
    float4 h1 = hr[q + G];
    asm volatile("red.global.add.v4.f32 [%0], {%1, %2, %3, %4};"
                 :: "l"(pr + q), "f"(h0.x * nrm), "f"(h0.y * nrm),
                    "f"(h0.z * nrm), "f"(h0.w * nrm) : "memory");
    asm volatile("red.global.add.v4.f32 [%0], {%1, %2, %3, %4};"
                 :: "l"(pr + q + G), "f"(h1.x * nrm), "f"(h1.y * nrm),
                    "f"(h1.z * nrm), "f"(h1.w * nrm) : "memory");
}

// ----------------------------------------------------------------
extern "C" void kernel_launch(void* const* d_in, const int* in_sizes, int n_in,
                              void* d_out, int out_size) {
    const float* x  = (const float*)d_in[0];
    const int*   ei = (const int*)d_in[1];
    const float* W1 = (const float*)d_in[2];
    const float* b1 = (const float*)d_in[3];
    const float* W2 = (const float*)d_in[4];
    const float* b2 = (const float*)d_in[5];
    const float* Wl = (const float*)d_in[6];
    const float* bl = (const float*)d_in[7];
    float*       out = (float*)d_out;

    int M = in_sizes[0] / 128;   // 100000
    int E = in_sizes[1] / 2;     // 1600000

    float* s = nullptr;
    cudaGetSymbolAddress((void**)&s, g_scratch);
    float* dinv   = s;
    float* h1agg  = dinv + NP;
    float* h2agg  = h1agg + (size_t)NP * 64;
    float* h      = h2agg + (size_t)NP * 32;
    float* t2     = h + (size_t)NP * 64;
    float* logits = t2 + (size_t)NP * 32;

    // zero dinv + h1agg + h2agg (contiguous 97*NP floats)
    k_zero<<<2048, THREADS>>>((float4*)dinv, NP * 97 / 4);

    k_deg<<<(E + THREADS - 1) / THREADS, THREADS>>>(ei, dinv, E);
    k_dinv<<<(M + THREADS - 1) / THREADS, THREADS>>>(dinv, M);

    int gb = NP / 128;           // 782

    // layer 1 (+ x@Wl0)
    k_gemm_f1<<<gb, 256>>>(x, W1, Wl, h, logits, M);
    k_scatter<16><<<E * 8 / THREADS, THREADS>>>(ei, dinv, h, h1agg, E);

    // layer 2 (+ h1@Wl1), epi1 fused into A-load
    k_gemm_f2<<<gb, 256>>>(h1agg, h, dinv, b1, W2, Wl, t2, logits);
    k_scatter<8><<<E * 4 / THREADS, THREADS>>>(ei, dinv, t2, h2agg, E);

    // final: epilogue-fused h2 @ Wl2 + bias + log_softmax -> out
    k_gemm_f3<<<gb, 128>>>(h2agg, t2, dinv, b2, Wl + 192 * 32, logits, bl, out, M);
}

// round 16
// speedup vs baseline: 1.6589x; 1.1923x over previous
#include <cuda_runtime.h>

#define N_NODES 100000
#define NP      100096   // 782 * 128
#define THREADS 256
#define E_EDGES 1600000

typedef unsigned long long u64;

// floats: dinv[NP] | h1agg[64NP] | h2agg[32NP] | h[64NP] | t2[32NP] | logits[32NP]
__device__ float g_scratch[(size_t)NP * 225];

// ---------------------------------------------------------------- f32x2 helpers
__device__ __forceinline__ u64 dup2(float f) {
    u64 r; asm("mov.b64 %0, {%1, %1};" : "=l"(r) : "f"(f)); return r;
}
__device__ __forceinline__ void fma2(u64& acc, u64 a, u64 b) {
    asm("fma.rn.f32x2 %0, %1, %2, %0;" : "+l"(acc) : "l"(a), "l"(b));
}
__device__ __forceinline__ float2 unp(u64 v) {
    float2 r; asm("mov.b64 {%0, %1}, %2;" : "=f"(r.x), "=f"(r.y) : "l"(v)); return r;
}

// ---------------------------------------------------------------- zero
__global__ void k_zero(float4* __restrict__ p, int n4) {
    int i = blockIdx.x * blockDim.x + threadIdx.x;
    int stride = gridDim.x * blockDim.x;
    float4 z = make_float4(0.f, 0.f, 0.f, 0.f);
    for (; i < n4; i += stride) p[i] = z;
}

// ---------------------------------------------------------------- degree (float RED into dinv buffer)
__global__ void k_deg(const int* __restrict__ ei, float* __restrict__ deg, int E) {
    int e = blockIdx.x * blockDim.x + threadIdx.x;
    if (e >= E) return;
    asm volatile("red.global.add.f32 [%0], %1;" :: "l"(deg + ei[E + e]), "f"(1.0f) : "memory");
}

__global__ void k_dinv(float* __restrict__ dinv, int N) {
    int i = blockIdx.x * blockDim.x + threadIdx.x;
    if (i < N) dinv[i] = rsqrtf(dinv[i] + 1.0f);
}

// ---------------------------------------------------------------- GEMM1: [h | logits] = x @ [W1 | Wl0]
// BM=128, BN=96 (64 H + 32 L), BK=16, 256 threads, TM=8(row-paired), TN=6, FFMA2
__global__ __launch_bounds__(256) void k_gemm_f1(
    const float* __restrict__ A, const float* __restrict__ W1, const float* __restrict__ Wl,
    float* __restrict__ H, float* __restrict__ L, int M) {
    __shared__ float As[16][132];
    __shared__ float Bs[16][96];
    int tid = threadIdx.x;
    int tr = tid >> 4, tc = tid & 15;
    int rowBase = blockIdx.x * 128;

    u64 accP[4][6];
#pragma unroll
    for (int i = 0; i < 4; i++)
#pragma unroll
        for (int j = 0; j < 6; j++) accP[i][j] = 0ull;

    for (int k0 = 0; k0 < 128; k0 += 16) {
#pragma unroll
        for (int t = 0; t < 2; t++) {
            int i = tid + t * 256;
            int r = i >> 2, c4 = i & 3;
            int gr = rowBase + r;
            float4 v = (gr < M) ? *(const float4*)(A + (size_t)gr * 128 + k0 + c4 * 4)
                                : make_float4(0.f, 0.f, 0.f, 0.f);
            As[c4 * 4 + 0][r] = v.x; As[c4 * 4 + 1][r] = v.y;
            As[c4 * 4 + 2][r] = v.z; As[c4 * 4 + 3][r] = v.w;
        }
#pragma unroll
        for (int t = 0; t < 6; t++) {
            int i = tid + t * 256;
            int r = i / 96, c = i - r * 96;
            Bs[r][c] = (c < 64) ? W1[(size_t)(k0 + r) * 64 + c]
                                : Wl[(size_t)(k0 + r) * 32 + (c - 64)];
        }
        __syncthreads();
#pragma unroll
        for (int kk = 0; kk < 16; kk++) {
            ulonglong2 a01 = *(const ulonglong2*)&As[kk][tr * 8];
            ulonglong2 a23 = *(const ulonglong2*)&As[kk][tr * 8 + 4];
            u64 aP[4] = {a01.x, a01.y, a23.x, a23.y};
            float4 b0 = *(const float4*)&Bs[kk][tc * 4];
            float2 b1 = *(const float2*)&Bs[kk][64 + tc * 2];
            u64 bP[6] = {dup2(b0.x), dup2(b0.y), dup2(b0.z),
                         dup2(b0.w), dup2(b1.x), dup2(b1.y)};
#pragma unroll
            for (int i = 0; i < 4; i++)
#pragma unroll
                for (int j = 0; j < 6; j++) fma2(accP[i][j], aP[i], bP[j]);
        }
        __syncthreads();
    }
#pragma unroll
    for (int i2 = 0; i2 < 4; i2++) {
        float2 c0 = unp(accP[i2][0]), c1 = unp(accP[i2][1]), c2 = unp(accP[i2][2]);
        float2 c3 = unp(accP[i2][3]), c4 = unp(accP[i2][4]), c5 = unp(accP[i2][5]);
        int gr = rowBase + tr * 8 + i2 * 2;   // < NP, scratch padded
        *(float4*)(H + (size_t)gr * 64 + tc * 4) = make_float4(c0.x, c1.x, c2.x, c3.x);
        *(float4*)(H + (size_t)(gr + 1) * 64 + tc * 4) = make_float4(c0.y, c1.y, c2.y, c3.y);
        *(float2*)(L + (size_t)gr * 32 + tc * 2) = make_float2(c4.x, c5.x);
        *(float2*)(L + (size_t)(gr + 1) * 32 + tc * 2) = make_float2(c4.y, c5.y);
    }
}

// ---------------------------------------------------------------- GEMM2 (epi1 fused in A-load), FFMA2:
// A_eff = relu(h1agg + h*dinv^2 + b1);  [t2 | logits+=] = A_eff @ [W2 | Wl1]
__global__ __launch_bounds__(256) void k_gemm_f2(
    const float* __restrict__ AGG, const float* __restrict__ H,
    const float* __restrict__ dinv, const float* __restrict__ b1,
    const float* __restrict__ W2, const float* __restrict__ Wl,
    float* __restrict__ T2, float* __restrict__ L) {
    __shared__ float As[16][132];
    __shared__ float Bs[16][64];
    int tid = threadIdx.x;
    int tr = tid >> 4, tc = tid & 15;
    int rowBase = blockIdx.x * 128;

    u64 accP[4][4];
#pragma unroll
    for (int i = 0; i < 4; i++)
#pragma unroll
        for (int j = 0; j < 4; j++) accP[i][j] = 0ull;

    for (int k0 = 0; k0 < 64; k0 += 16) {
#pragma unroll
        for (int t = 0; t < 2; t++) {
            int i = tid + t * 256;
            int r = i >> 2, c4 = i & 3;
            int gr = rowBase + r;
            float di = dinv[gr]; float d2 = di * di;
            float4 ag = *(const float4*)(AGG + (size_t)gr * 64 + k0 + c4 * 4);
            float4 hv = *(const float4*)(H   + (size_t)gr * 64 + k0 + c4 * 4);
            float4 bv = *(const float4*)(b1 + k0 + c4 * 4);
            As[c4 * 4 + 0][r] = fmaxf(ag.x + hv.x * d2 + bv.x, 0.f);
            As[c4 * 4 + 1][r] = fmaxf(ag.y + hv.y * d2 + bv.y, 0.f);
            As[c4 * 4 + 2][r] = fmaxf(ag.z + hv.z * d2 + bv.z, 0.f);
            As[c4 * 4 + 3][r] = fmaxf(ag.w + hv.w * d2 + bv.w, 0.f);
        }
#pragma unroll
        for (int t = 0; t < 4; t++) {
            int i = tid + t * 256;
            int r = i >> 6, c = i & 63;
            Bs[r][c] = (c < 32) ? W2[(size_t)(k0 + r) * 32 + c]
                                : Wl[(size_t)(128 + k0 + r) * 32 + (c - 32)];
        }
        __syncthreads();
#pragma unroll
        for (int kk = 0; kk < 16; kk++) {
            ulonglong2 a01 = *(const ulonglong2*)&As[kk][tr * 8];
            ulonglong2 a23 = *(const ulonglong2*)&As[kk][tr * 8 + 4];
            u64 aP[4] = {a01.x, a01.y, a23.x, a23.y};
            float4 b0 = *(const float4*)&Bs[kk][tc * 4];
            u64 bP[4] = {dup2(b0.x), dup2(b0.y), dup2(b0.z), dup2(b0.w)};
#pragma unroll
            for (int i = 0; i < 4; i++)
#pragma unroll
                for (int j = 0; j < 4; j++) fma2(accP[i][j], aP[i], bP[j]);
        }
        __syncthreads();
    }
#pragma unroll
    for (int i2 = 0; i2 < 4; i2++) {
        float2 c0 = unp(accP[i2][0]), c1 = unp(accP[i2][1]);
        float2 c2 = unp(accP[i2][2]), c3 = unp(accP[i2][3]);
        int gr = rowBase + tr * 8 + i2 * 2;
        if (tc < 8) {
            *(float4*)(T2 + (size_t)gr * 32 + tc * 4) = make_float4(c0.x, c1.x, c2.x, c3.x);
            *(float4*)(T2 + (size_t)(gr + 1) * 32 + tc * 4) = make_float4(c0.y, c1.y, c2.y, c3.y);
        } else {
            float* p0 = L + (size_t)gr * 32 + (tc - 8) * 4;
            float* p1 = L + (size_t)(gr + 1) * 32 + (tc - 8) * 4;
            float4 o0 = *(float4*)p0;
            float4 o1 = *(float4*)p1;
            *(float4*)p0 = make_float4(o0.x + c0.x, o0.y + c1.x, o0.z + c2.x, o0.w + c3.x);
            *(float4*)p1 = make_float4(o1.x + c0.y, o1.y + c1.y, o1.z + c2.y, o1.w + c3.y);
        }
    }
}

// ---------------------------------------------------------------- GEMM3 (+ log_softmax epilogue -> out), FFMA2
__global__ __launch_bounds__(128) void k_gemm_f3(
    const float* __restrict__ AGG, const float* __restrict__ T2,
    const float* __restrict__ dinv, const float* __restrict__ b2,
    const float* __restrict__ Wl2, const float* __restrict__ L,
    const float* __restrict__ bl, float* __restrict__ out, int M) {
    __shared__ float As[32][132];
    __shared__ float Bs[32][32];
    int tid = threadIdx.x;
    int tr = tid >> 3, tc = tid & 7;
    int rowBase = blockIdx.x * 128;

    for (int i = tid; i < 1024; i += 128) {
        int r = i >> 3, c4 = i & 7;
        int gr = rowBase + r;
        float di = dinv[gr]; float d2 = di * di;
        float4 ag = *(const float4*)(AGG + (size_t)gr * 32 + c4 * 4);
        float4 tv = *(const float4*)(T2  + (size_t)gr * 32 + c4 * 4);
        float4 bv = *(const float4*)(b2 + c4 * 4);
        As[c4 * 4 + 0][r] = ag.x + tv.x * d2 + bv.x;
        As[c4 * 4 + 1][r] = ag.y + tv.y * d2 + bv.y;
        As[c4 * 4 + 2][r] = ag.z + tv.z * d2 + bv.z;
        As[c4 * 4 + 3][r] = ag.w + tv.w * d2 + bv.w;
    }
    for (int i = tid; i < 1024; i += 128) Bs[i >> 5][i & 31] = Wl2[i];
    __syncthreads();

    u64 accP[4][4];
#pragma unroll
    for (int i = 0; i < 4; i++)
#pragma unroll
        for (int j = 0; j < 4; j++) accP[i][j] = 0ull;
#pragma unroll
    for (int kk = 0; kk < 32; kk++) {
        ulonglong2 a01 = *(const ulonglong2*)&As[kk][tr * 8];
        ulonglong2 a23 = *(const ulonglong2*)&As[kk][tr * 8 + 4];
        u64 aP[4] = {a01.x, a01.y, a23.x, a23.y};
        float4 b0 = *(const float4*)&Bs[kk][tc * 4];
        u64 bP[4] = {dup2(b0.x), dup2(b0.y), dup2(b0.z), dup2(b0.w)};
#pragma unroll
        for (int i = 0; i < 4; i++)
#pragma unroll
            for (int j = 0; j < 4; j++) fma2(accP[i][j], aP[i], bP[j]);
    }

    float4 blv = *(const float4*)(bl + tc * 4);
#pragma unroll
    for (int i2 = 0; i2 < 4; i2++) {
        float2 c0 = unp(accP[i2][0]), c1 = unp(accP[i2][1]);
        float2 c2 = unp(accP[i2][2]), c3 = unp(accP[i2][3]);
#pragma unroll
        for (int half = 0; half < 2; half++) {
            int gr = rowBase + tr * 8 + i2 * 2 + half;
            float4 old = *(const float4*)(L + (size_t)gr * 32 + tc * 4);
            float v0 = (half ? c0.y : c0.x) + old.x + blv.x;
            float v1 = (half ? c1.y : c1.x) + old.y + blv.y;
            float v2 = (half ? c2.y : c2.x) + old.z + blv.z;
            float v3 = (half ? c3.y : c3.x) + old.w + blv.w;
            float m = fmaxf(fmaxf(v0, v1), fmaxf(v2, v3));
#pragma unroll
            for (int o = 1; o < 8; o <<= 1) m = fmaxf(m, __shfl_xor_sync(0xffffffffu, m, o, 8));
            float s = expf(v0 - m) + expf(v1 - m) + expf(v2 - m) + expf(v3 - m);
#pragma unroll
            for (int o = 1; o < 8; o <<= 1) s += __shfl_xor_sync(0xffffffffu, s, o, 8);
            float ml = m + logf(s);
            if (gr < M)
                *(float4*)(out + (size_t)gr * 32 + tc * 4) =
                    make_float4(v0 - ml, v1 - ml, v2 - ml, v3 - ml);
        }
    }
}

// ---------------------------------------------------------------- edge scatter: 2x RED.v4 per thread
template<int C4>
__global__ void k_scatter(const int* __restrict__ ei, const float* __restrict__ dinv,
                          const float* __restrict__ h, float* __restrict__ agg, int E) {
    constexpr int G = C4 / 2;
    int idx = blockIdx.x * blockDim.x + threadIdx.x;
    int lane = threadIdx.x & 31;
    int e = idx / G;
    int q = idx & (G - 1);
    int s = 0, d = 0;
    float nrm = 0.f;
    if ((lane & (G - 1)) == 0) {
        s = ei[e];
        d = ei[E + e];
        nrm = dinv[s] * dinv[d];
    }
    int src = lane & ~(G - 1);
    s   = __shfl_sync(0xffffffffu, s,   src);
    d   = __shfl_sync(0xffffffffu, d,   src);
    nrm = __shfl_sync(0xffffffffu, nrm, src);
    const float4* hr = reinterpret_cast<const float4*>(h) + (size_t)s * C4;
    float4*       pr = reinterpret_cast<float4*>(agg) + (size_t)d * C4;
    float4 h0 = hr[q];
    float4 h1 = hr[q + G];
    asm volatile("red.global.add.v4.f32 [%0], {%1, %2, %3, %4};"
                 :: "l"(pr + q), "f"(h0.x * nrm), "f"(h0.y * nrm),
                    "f"(h0.z * nrm), "f"(h0.w * nrm) : "memory");
    asm volatile("red.global.add.v4.f32 [%0], {%1, %2, %3, %4};"
                 :: "l"(pr + q + G), "f"(h1.x * nrm), "f"(h1.y * nrm),
                    "f"(h1.z * nrm), "f"(h1.w * nrm) : "memory");
}

// ----------------------------------------------------------------
extern "C" void kernel_launch(void* const* d_in, const int* in_sizes, int n_in,
                              void* d_out, int out_size) {
    const float* x  = (const float*)d_in[0];
    const int*   ei = (const int*)d_in[1];
    const float* W1 = (const float*)d_in[2];
    const float* b1 = (const float*)d_in[3];
    const float* W2 = (const float*)d_in[4];
    const float* b2 = (const float*)d_in[5];
    const float* Wl = (const float*)d_in[6];
    const float* bl = (const float*)d_in[7];
    float*       out = (float*)d_out;

    int M = in_sizes[0] / 128;   // 100000
    int E = in_sizes[1] / 2;     // 1600000

    float* s = nullptr;
    cudaGetSymbolAddress((void**)&s, g_scratch);
    float* dinv   = s;
    float* h1agg  = dinv + NP;
    float* h2agg  = h1agg + (size_t)NP * 64;
    float* h      = h2agg + (size_t)NP * 32;
    float* t2     = h + (size_t)NP * 64;
    float* logits = t2 + (size_t)NP * 32;

    // side stream + events (created once on the uncaptured correctness call)
    static cudaStream_t s2 = nullptr;
    static cudaEvent_t evF = nullptr, evJ = nullptr;
    if (!s2) {
        cudaStreamCreateWithFlags(&s2, cudaStreamNonBlocking);
        cudaEventCreateWithFlags(&evF, cudaEventDisableTiming);
        cudaEventCreateWithFlags(&evJ, cudaEventDisableTiming);
    }

    // fork: prep chain (zero, deg, dinv) on s2 concurrent with GEMM1 on main
    cudaEventRecord(evF, 0);
    cudaStreamWaitEvent(s2, evF, 0);
    k_zero<<<2048, THREADS, 0, s2>>>((float4*)dinv, NP * 97 / 4);
    k_deg<<<(E + THREADS - 1) / THREADS, THREADS, 0, s2>>>(ei, dinv, E);
    k_dinv<<<(M + THREADS - 1) / THREADS, THREADS, 0, s2>>>(dinv, M);
    cudaEventRecord(evJ, s2);

    int gb = NP / 128;           // 782

    // layer 1 (+ x@Wl0) on main stream, overlapped with prep
    k_gemm_f1<<<gb, 256>>>(x, W1, Wl, h, logits, M);

    // join before scatter (needs dinv + zeroed h1agg)
    cudaStreamWaitEvent(0, evJ, 0);
    k_scatter<16><<<E * 8 / THREADS, THREADS>>>(ei, dinv, h, h1agg, E);

    // layer 2 (+ h1@Wl1), epi1 fused into A-load
    k_gemm_f2<<<gb, 256>>>(h1agg, h, dinv, b1, W2, Wl, t2, logits);
    k_scatter<8><<<E * 4 / THREADS, THREADS>>>(ei, dinv, t2, h2agg, E);

    // final: epilogue-fused h2 @ Wl2 + bias + log_softmax -> out
    k_gemm_f3<<<gb, 128>>>(h2agg, t2, dinv, b2, Wl + 192 * 32, logits, bl, out, M);
}

// round 17
// speedup vs baseline: 1.7463x; 1.0527x over previous
#include <cuda_runtime.h>

#define N_NODES 100000
#define NP      100096   // 782 * 128
#define THREADS 256
#define E_EDGES 1600000

typedef unsigned long long u64;

// floats: dinv[NP] | h1agg[64NP] | h2agg[32NP] | h[64NP] | t2[32NP] | logits[32NP]
__device__ float g_scratch[(size_t)NP * 225];

// ---------------------------------------------------------------- f32x2 helpers
__device__ __forceinline__ u64 dup2(float f) {
    u64 r; asm("mov.b64 %0, {%1, %1};" : "=l"(r) : "f"(f)); return r;
}
__device__ __forceinline__ void fma2(u64& acc, u64 a, u64 b) {
    asm("fma.rn.f32x2 %0, %1, %2, %0;" : "+l"(acc) : "l"(a), "l"(b));
}
__device__ __forceinline__ float2 unp(u64 v) {
    float2 r; asm("mov.b64 {%0, %1}, %2;" : "=f"(r.x), "=f"(r.y) : "l"(v)); return r;
}

// ---------------------------------------------------------------- zero
__global__ void k_zero(float4* __restrict__ p, int n4) {
    int i = blockIdx.x * blockDim.x + threadIdx.x;
    int stride = gridDim.x * blockDim.x;
    float4 z = make_float4(0.f, 0.f, 0.f, 0.f);
    for (; i < n4; i += stride) p[i] = z;
}

// ---------------------------------------------------------------- degree (float RED into dinv buffer)
__global__ void k_deg(const int* __restrict__ ei, float* __restrict__ deg, int E) {
    int e = blockIdx.x * blockDim.x + threadIdx.x;
    if (e >= E) return;
    asm volatile("red.global.add.f32 [%0], %1;" :: "l"(deg + ei[E + e]), "f"(1.0f) : "memory");
}

__global__ void k_dinv(float* __restrict__ dinv, int N) {
    int i = blockIdx.x * blockDim.x + threadIdx.x;
    if (i < N) dinv[i] = rsqrtf(dinv[i] + 1.0f);
}

// ---------------------------------------------------------------- GEMM H: H = x @ W1  (K=128, N=64), FFMA2
__global__ __launch_bounds__(256) void k_gemm_h(
    const float* __restrict__ A, const float* __restrict__ W1,
    float* __restrict__ H, int M) {
    __shared__ float As[16][132];
    __shared__ float Bs[16][64];
    int tid = threadIdx.x;
    int tr = tid >> 4, tc = tid & 15;
    int rowBase = blockIdx.x * 128;

    u64 accP[4][4];
#pragma unroll
    for (int i = 0; i < 4; i++)
#pragma unroll
        for (int j = 0; j < 4; j++) accP[i][j] = 0ull;

    for (int k0 = 0; k0 < 128; k0 += 16) {
#pragma unroll
        for (int t = 0; t < 2; t++) {
            int i = tid + t * 256;
            int r = i >> 2, c4 = i & 3;
            int gr = rowBase + r;
            float4 v = (gr < M) ? *(const float4*)(A + (size_t)gr * 128 + k0 + c4 * 4)
                                : make_float4(0.f, 0.f, 0.f, 0.f);
            As[c4 * 4 + 0][r] = v.x; As[c4 * 4 + 1][r] = v.y;
            As[c4 * 4 + 2][r] = v.z; As[c4 * 4 + 3][r] = v.w;
        }
#pragma unroll
        for (int t = 0; t < 4; t++) {
            int i = tid + t * 256;
            int r = i >> 6, c = i & 63;
            Bs[r][c] = W1[(size_t)(k0 + r) * 64 + c];
        }
        __syncthreads();
#pragma unroll
        for (int kk = 0; kk < 16; kk++) {
            ulonglong2 a01 = *(const ulonglong2*)&As[kk][tr * 8];
            ulonglong2 a23 = *(const ulonglong2*)&As[kk][tr * 8 + 4];
            u64 aP[4] = {a01.x, a01.y, a23.x, a23.y};
            float4 b0 = *(const float4*)&Bs[kk][tc * 4];
            u64 bP[4] = {dup2(b0.x), dup2(b0.y), dup2(b0.z), dup2(b0.w)};
#pragma unroll
            for (int i = 0; i < 4; i++)
#pragma unroll
                for (int j = 0; j < 4; j++) fma2(accP[i][j], aP[i], bP[j]);
        }
        __syncthreads();
    }
#pragma unroll
    for (int i2 = 0; i2 < 4; i2++) {
        float2 c0 = unp(accP[i2][0]), c1 = unp(accP[i2][1]);
        float2 c2 = unp(accP[i2][2]), c3 = unp(accP[i2][3]);
        int gr = rowBase + tr * 8 + i2 * 2;   // < NP, scratch padded
        *(float4*)(H + (size_t)gr * 64 + tc * 4) = make_float4(c0.x, c1.x, c2.x, c3.x);
        *(float4*)(H + (size_t)(gr + 1) * 64 + tc * 4) = make_float4(c0.y, c1.y, c2.y, c3.y);
    }
}

// ---------------------------------------------------------------- GEMM L1: L = x @ Wl0  (K=128, N=32), 128 thr, FFMA2
__global__ __launch_bounds__(128) void k_gemm_l1(
    const float* __restrict__ A, const float* __restrict__ Wl,
    float* __restrict__ L, int M) {
    __shared__ float As[16][132];
    __shared__ float Bs[16][32];
    int tid = threadIdx.x;
    int tr = tid >> 3, tc = tid & 7;
    int rowBase = blockIdx.x * 128;

    u64 accP[4][4];
#pragma unroll
    for (int i = 0; i < 4; i++)
#pragma unroll
        for (int j = 0; j < 4; j++) accP[i][j] = 0ull;

    for (int k0 = 0; k0 < 128; k0 += 16) {
#pragma unroll
        for (int t = 0; t < 4; t++) {
            int i = tid + t * 128;
            int r = i >> 2, c4 = i & 3;
            int gr = rowBase + r;
            float4 v = (gr < M) ? *(const float4*)(A + (size_t)gr * 128 + k0 + c4 * 4)
                                : make_float4(0.f, 0.f, 0.f, 0.f);
            As[c4 * 4 + 0][r] = v.x; As[c4 * 4 + 1][r] = v.y;
            As[c4 * 4 + 2][r] = v.z; As[c4 * 4 + 3][r] = v.w;
        }
#pragma unroll
        for (int t = 0; t < 4; t++) {
            int i = tid + t * 128;
            int r = i >> 5, c = i & 31;
            Bs[r][c] = Wl[(size_t)(k0 + r) * 32 + c];
        }
        __syncthreads();
#pragma unroll
        for (int kk = 0; kk < 16; kk++) {
            ulonglong2 a01 = *(const ulonglong2*)&As[kk][tr * 8];
            ulonglong2 a23 = *(const ulonglong2*)&As[kk][tr * 8 + 4];
            u64 aP[4] = {a01.x, a01.y, a23.x, a23.y};
            float4 b0 = *(const float4*)&Bs[kk][tc * 4];
            u64 bP[4] = {dup2(b0.x), dup2(b0.y), dup2(b0.z), dup2(b0.w)};
#pragma unroll
            for (int i = 0; i < 4; i++)
#pragma unroll
                for (int j = 0; j < 4; j++) fma2(accP[i][j], aP[i], bP[j]);
        }
        __syncthreads();
    }
#pragma unroll
    for (int i2 = 0; i2 < 4; i2++) {
        float2 c0 = unp(accP[i2][0]), c1 = unp(accP[i2][1]);
        float2 c2 = unp(accP[i2][2]), c3 = unp(accP[i2][3]);
        int gr = rowBase + tr * 8 + i2 * 2;
        *(float4*)(L + (size_t)gr * 32 + tc * 4) = make_float4(c0.x, c1.x, c2.x, c3.x);
        *(float4*)(L + (size_t)(gr + 1) * 32 + tc * 4) = make_float4(c0.y, c1.y, c2.y, c3.y);
    }
}

// ---------------------------------------------------------------- GEMM2 core: A_eff = relu(AGG + H*dinv^2 + b1), 128 thr
// ACCUM=false: OUT = A_eff @ B (B=W2, -> t2); ACCUM=true: OUT += A_eff @ B (B=Wl1, -> L)
template<bool ACCUM>
__global__ __launch_bounds__(128) void k_gemm2(
    const float* __restrict__ AGG, const float* __restrict__ H,
    const float* __restrict__ dinv, const float* __restrict__ b1,
    const float* __restrict__ B, float* __restrict__ OUT) {
    __shared__ float As[16][132];
    __shared__ float Bs[16][32];
    int tid = threadIdx.x;
    int tr = tid >> 3, tc = tid & 7;
    int rowBase = blockIdx.x * 128;

    u64 accP[4][4];
#pragma unroll
    for (int i = 0; i < 4; i++)
#pragma unroll
        for (int j = 0; j < 4; j++) accP[i][j] = 0ull;

    for (int k0 = 0; k0 < 64; k0 += 16) {
#pragma unroll
        for (int t = 0; t < 4; t++) {
            int i = tid + t * 128;
            int r = i >> 2, c4 = i & 3;
            int gr = rowBase + r;
            float di = dinv[gr]; float d2 = di * di;
            float4 ag = *(const float4*)(AGG + (size_t)gr * 64 + k0 + c4 * 4);
            float4 hv = *(const float4*)(H   + (size_t)gr * 64 + k0 + c4 * 4);
            float4 bv = *(const float4*)(b1 + k0 + c4 * 4);
            As[c4 * 4 + 0][r] = fmaxf(ag.x + hv.x * d2 + bv.x, 0.f);
            As[c4 * 4 + 1][r] = fmaxf(ag.y + hv.y * d2 + bv.y, 0.f);
            As[c4 * 4 + 2][r] = fmaxf(ag.z + hv.z * d2 + bv.z, 0.f);
            As[c4 * 4 + 3][r] = fmaxf(ag.w + hv.w * d2 + bv.w, 0.f);
        }
#pragma unroll
        for (int t = 0; t < 4; t++) {
            int i = tid + t * 128;
            int r = i >> 5, c = i & 31;
            Bs[r][c] = B[(size_t)(k0 + r) * 32 + c];
        }
        __syncthreads();
#pragma unroll
        for (int kk = 0; kk < 16; kk++) {
            ulonglong2 a01 = *(const ulonglong2*)&As[kk][tr * 8];
            ulonglong2 a23 = *(const ulonglong2*)&As[kk][tr * 8 + 4];
            u64 aP[4] = {a01.x, a01.y, a23.x, a23.y};
            float4 b0 = *(const float4*)&Bs[kk][tc * 4];
            u64 bP[4] = {dup2(b0.x), dup2(b0.y), dup2(b0.z), dup2(b0.w)};
#pragma unroll
            for (int i = 0; i < 4; i++)
#pragma unroll
                for (int j = 0; j < 4; j++) fma2(accP[i][j], aP[i], bP[j]);
        }
        __syncthreads();
    }
#pragma unroll
    for (int i2 = 0; i2 < 4; i2++) {
        float2 c0 = unp(accP[i2][0]), c1 = unp(accP[i2][1]);
        float2 c2 = unp(accP[i2][2]), c3 = unp(accP[i2][3]);
        int gr = rowBase + tr * 8 + i2 * 2;
        float* p0 = OUT + (size_t)gr * 32 + tc * 4;
        float* p1 = OUT + (size_t)(gr + 1) * 32 + tc * 4;
        if (ACCUM) {
            float4 o0 = *(float4*)p0;
            float4 o1 = *(float4*)p1;
            *(float4*)p0 = make_float4(o0.x + c0.x, o0.y + c1.x, o0.z + c2.x, o0.w + c3.x);
            *(float4*)p1 = make_float4(o1.x + c0.y, o1.y + c1.y, o1.z + c2.y, o1.w + c3.y);
        } else {
            *(float4*)p0 = make_float4(c0.x, c1.x, c2.x, c3.x);
            *(float4*)p1 = make_float4(c0.y, c1.y, c2.y, c3.y);
        }
    }
}

// ---------------------------------------------------------------- GEMM3 (+ log_softmax epilogue -> out), FFMA2
__global__ __launch_bounds__(128) void k_gemm_f3(
    const float* __restrict__ AGG, const float* __restrict__ T2,
    const float* __restrict__ dinv, const float* __restrict__ b2,
    const float* __restrict__ Wl2, const float* __restrict__ L,
    const float* __restrict__ bl, float* __restrict__ out, int M) {
    __shared__ float As[32][132];
    __shared__ float Bs[32][32];
    int tid = threadIdx.x;
    int tr = tid >> 3, tc = tid & 7;
    int rowBase = blockIdx.x * 128;

    for (int i = tid; i < 1024; i += 128) {
        int r = i >> 3, c4 = i & 7;
        int gr = rowBase + r;
        float di = dinv[gr]; float d2 = di * di;
        float4 ag = *(const float4*)(AGG + (size_t)gr * 32 + c4 * 4);
        float4 tv = *(const float4*)(T2  + (size_t)gr * 32 + c4 * 4);
        float4 bv = *(const float4*)(b2 + c4 * 4);
        As[c4 * 4 + 0][r] = ag.x + tv.x * d2 + bv.x;
        As[c4 * 4 + 1][r] = ag.y + tv.y * d2 + bv.y;
        As[c4 * 4 + 2][r] = ag.z + tv.z * d2 + bv.z;
        As[c4 * 4 + 3][r] = ag.w + tv.w * d2 + bv.w;
    }
    for (int i = tid; i < 1024; i += 128) Bs[i >> 5][i & 31] = Wl2[i];
    __syncthreads();

    u64 accP[4][4];
#pragma unroll
    for (int i = 0; i < 4; i++)
#pragma unroll
        for (int j = 0; j < 4; j++) accP[i][j] = 0ull;
#pragma unroll
    for (int kk = 0; kk < 32; kk++) {
        ulonglong2 a01 = *(const ulonglong2*)&As[kk][tr * 8];
        ulonglong2 a23 = *(const ulonglong2*)&As[kk][tr * 8 + 4];
        u64 aP[4] = {a01.x, a01.y, a23.x, a23.y};
        float4 b0 = *(const float4*)&Bs[kk][tc * 4];
        u64 bP[4] = {dup2(b0.x), dup2(b0.y), dup2(b0.z), dup2(b0.w)};
#pragma unroll
        for (int i = 0; i < 4; i++)
#pragma unroll
            for (int j = 0; j < 4; j++) fma2(accP[i][j], aP[i], bP[j]);
    }

    float4 blv = *(const float4*)(bl + tc * 4);
#pragma unroll
    for (int i2 = 0; i2 < 4; i2++) {
        float2 c0 = unp(accP[i2][0]), c1 = unp(accP[i2][1]);
        float2 c2 = unp(accP[i2][2]), c3 = unp(accP[i2][3]);
#pragma unroll
        for (int half = 0; half < 2; half++) {
            int gr = rowBase + tr * 8 + i2 * 2 + half;
            float4 old = *(const float4*)(L + (size_t)gr * 32 + tc * 4);
            float v0 = (half ? c0.y : c0.x) + old.x + blv.x;
            float v1 = (half ? c1.y : c1.x) + old.y + blv.y;
            float v2 = (half ? c2.y : c2.x) + old.z + blv.z;
            float v3 = (half ? c3.y : c3.x) + old.w + blv.w;
            float m = fmaxf(fmaxf(v0, v1), fmaxf(v2, v3));
#pragma unroll
            for (int o = 1; o < 8; o <<= 1) m = fmaxf(m, __shfl_xor_sync(0xffffffffu, m, o, 8));
            float s = expf(v0 - m) + expf(v1 - m) + expf(v2 - m) + expf(v3 - m);
#pragma unroll
            for (int o = 1; o < 8; o <<= 1) s += __shfl_xor_sync(0xffffffffu, s, o, 8);
            float ml = m + logf(s);
            if (gr < M)
                *(float4*)(out + (size_t)gr * 32 + tc * 4) =
                    make_float4(v0 - ml, v1 - ml, v2 - ml, v3 - ml);
        }
    }
}

// ---------------------------------------------------------------- edge scatter: 2x RED.v4 per thread
template<int C4>
__global__ void k_scatter(const int* __restrict__ ei, const float* __restrict__ dinv,
                          const float* __restrict__ h, float* __restrict__ agg, int E) {
    constexpr int G = C4 / 2;
    int idx = blockIdx.x * blockDim.x + threadIdx.x;
    int lane = threadIdx.x & 31;
    int e = idx / G;
    int q = idx & (G - 1);
    int s = 0, d = 0;
    float nrm = 0.f;
    if ((lane & (G - 1)) == 0) {
        s = ei[e];
        d = ei[E + e];
        nrm = dinv[s] * dinv[d];
    }
    int src = lane & ~(G - 1);
    s   = __shfl_sync(0xffffffffu, s,   src);
    d   = __shfl_sync(0xffffffffu, d,   src);
    nrm = __shfl_sync(0xffffffffu, nrm, src);
    const float4* hr = reinterpret_cast<const float4*>(h) + (size_t)s * C4;
    float4*       pr = reinterpret_cast<float4*>(agg) + (size_t)d * C4;
    float4 h0 = hr[q];
    float4 h1 = hr[q + G];
    asm volatile("red.global.add.v4.f32 [%0], {%1, %2, %3, %4};"
                 :: "l"(pr + q), "f"(h0.x * nrm), "f"(h0.y * nrm),
                    "f"(h0.z * nrm), "f"(h0.w * nrm) : "memory");
    asm volatile("red.global.add.v4.f32 [%0], {%1, %2, %3, %4};"
                 :: "l"(pr + q + G), "f"(h1.x * nrm), "f"(h1.y * nrm),
                    "f"(h1.z * nrm), "f"(h1.w * nrm) : "memory");
}

// ----------------------------------------------------------------
extern "C" void kernel_launch(void* const* d_in, const int* in_sizes, int n_in,
                              void* d_out, int out_size) {
    const float* x  = (const float*)d_in[0];
    const int*   ei = (const int*)d_in[1];
    const float* W1 = (const float*)d_in[2];
    const float* b1 = (const float*)d_in[3];
    const float* W2 = (const float*)d_in[4];
    const float* b2 = (const float*)d_in[5];
    const float* Wl = (const float*)d_in[6];
    const float* bl = (const float*)d_in[7];
    float*       out = (float*)d_out;

    int M = in_sizes[0] / 128;   // 100000
    int E = in_sizes[1] / 2;     // 1600000

    float* s = nullptr;
    cudaGetSymbolAddress((void**)&s, g_scratch);
    float* dinv   = s;
    float* h1agg  = dinv + NP;
    float* h2agg  = h1agg + (size_t)NP * 64;
    float* h      = h2agg + (size_t)NP * 32;
    float* t2     = h + (size_t)NP * 64;
    float* logits = t2 + (size_t)NP * 32;

    static cudaStream_t s2 = nullptr;
    static cudaEvent_t evF = nullptr, evPrep = nullptr, evS1 = nullptr, evJ3 = nullptr;
    if (!s2) {
        cudaStreamCreateWithFlags(&s2, cudaStreamNonBlocking);
        cudaEventCreateWithFlags(&evF,    cudaEventDisableTiming);
        cudaEventCreateWithFlags(&evPrep, cudaEventDisableTiming);
        cudaEventCreateWithFlags(&evS1,   cudaEventDisableTiming);
        cudaEventCreateWithFlags(&evJ3,   cudaEventDisableTiming);
    }

    int gb = NP / 128;           // 782

    // fork side stream
    cudaEventRecord(evF, 0);
    cudaStreamWaitEvent(s2, evF, 0);

    // s2: prep chain, then L = x@Wl0 (independent of main)
    k_zero<<<2048, THREADS, 0, s2>>>((float4*)dinv, NP * 97 / 4);
    k_deg<<<(E + THREADS - 1) / THREADS, THREADS, 0, s2>>>(ei, dinv, E);
    k_dinv<<<(M + THREADS - 1) / THREADS, THREADS, 0, s2>>>(dinv, M);
    cudaEventRecord(evPrep, s2);
    k_gemm_l1<<<gb, 128, 0, s2>>>(x, Wl, logits, M);

    // main: H = x@W1, then scatter16 (needs H + prep)
    k_gemm_h<<<gb, 256>>>(x, W1, h, M);
    cudaStreamWaitEvent(0, evPrep, 0);
    k_scatter<16><<<E * 8 / THREADS, THREADS>>>(ei, dinv, h, h1agg, E);
    cudaEventRecord(evS1, 0);

    // s2: logits += A_eff@Wl1 (needs scatter16 + L from k_gemm_l1)
    cudaStreamWaitEvent(s2, evS1, 0);
    k_gemm2<true><<<gb, 128, 0, s2>>>(h1agg, h, dinv, b1, Wl + 128 * 32, logits);
    cudaEventRecord(evJ3, s2);

    // main: t2 = A_eff@W2, scatter8, final GEMM3 (+log_softmax)
    k_gemm2<false><<<gb, 128>>>(h1agg, h, dinv, b1, W2, t2);
    k_scatter<8><<<E * 4 / THREADS, THREADS>>>(ei, dinv, t2, h2agg, E);
    cudaStreamWaitEvent(0, evJ3, 0);
    k_gemm_f3<<<gb, 128>>>(h2agg, t2, dinv, b2, Wl + 192 * 32, logits, bl, out, M);
}